// round 1
// baseline (speedup 1.0000x reference)
#include <cuda_runtime.h>
#include <cuda_bf16.h>
#include <math.h>

// Problem constants
#define Bn 4
#define Ln 1024
#define Dn 512
#define Hn 8
#define DH 64
#define BHn 32           // B*H
#define EMB_ROWS 2047    // 2L-1

// ---------------- scratch (device globals; no cudaMalloc allowed) ----------
__device__ float g_emb[2048 * 64];                 // row 2047 padding (zero-init)
__device__ float g_q[BHn * Ln * DH];
__device__ float g_k[BHn * Ln * DH];
__device__ float g_v[BHn * Ln * DH];
__device__ float g_S[(size_t)BHn * Ln * Ln];       // 134 MB scores scratch

// ---------------- kernel 1: sinusoidal embeddings ---------------------------
__global__ void emb_kernel() {
    int r = blockIdx.x;           // 0..2046
    int j = threadIdx.x;          // 0..31
    float pos = (float)(r - (Ln - 1));
    const float c = (float)(9.210340371976184 / 64.0);   // ln(10000)/64
    float div = expf(-(2.0f * (float)j) * c);
    float a = pos * div;
    g_emb[r * 64 + j]      = sinf(a);
    g_emb[r * 64 + 32 + j] = cosf(a);
}

// ---------------- kernel 2: proj GEMM (x@W + b) -> Q,K,V scatter ------------
// M=4096, N=1536, K=512. 128x128x32 tiles, 256 threads, 8x8 per thread.
__global__ __launch_bounds__(256) void proj_kernel(const float* __restrict__ x,
                                                   const float* __restrict__ W,
                                                   const float* __restrict__ bias) {
    __shared__ float As[128 * 33];   // [m][k], pad 33
    __shared__ float Bs[32 * 132];   // [k][n], pad 132 (float4-aligned)
    int bn = blockIdx.x;             // 0..11
    int bm = blockIdx.y;             // 0..31
    int m0 = bm * 128, n0 = bn * 128;
    int tid = threadIdx.x;
    int tx = tid & 15, ty = tid >> 4;

    float acc[8][4 * 2];
    float accv[8][8];
    #pragma unroll
    for (int i = 0; i < 8; i++)
        #pragma unroll
        for (int j = 0; j < 8; j++) accv[i][j] = 0.0f;
    (void)acc;

    for (int k0 = 0; k0 < 512; k0 += 32) {
        // load A tile 128x32 (full 128B rows coalesced)
        #pragma unroll
        for (int p = 0; p < 4; p++) {
            int r = (tid >> 3) + p * 32;
            int c = (tid & 7) * 4;
            float4 v = *(const float4*)(x + (size_t)(m0 + r) * 512 + k0 + c);
            float* a = As + r * 33 + c;
            a[0] = v.x; a[1] = v.y; a[2] = v.z; a[3] = v.w;
        }
        // load B tile 32x128 (full 512B rows coalesced)
        #pragma unroll
        for (int p = 0; p < 4; p++) {
            int r = (tid >> 5) + p * 8;
            int c = (tid & 31) * 4;
            float4 v = *(const float4*)(W + (size_t)(k0 + r) * 1536 + n0 + c);
            *(float4*)(Bs + r * 132 + c) = v;
        }
        __syncthreads();
        #pragma unroll
        for (int kk = 0; kk < 32; kk++) {
            float a[8], b[8];
            #pragma unroll
            for (int ii = 0; ii < 8; ii++) a[ii] = As[(ty * 8 + ii) * 33 + kk];
            #pragma unroll
            for (int jj = 0; jj < 8; jj++) b[jj] = Bs[kk * 132 + tx + 16 * jj];
            #pragma unroll
            for (int ii = 0; ii < 8; ii++)
                #pragma unroll
                for (int jj = 0; jj < 8; jj++) accv[ii][jj] += a[ii] * b[jj];
        }
        __syncthreads();
    }
    // epilogue: add bias, scatter to Q/K/V [B,H,L,64]
    #pragma unroll
    for (int ii = 0; ii < 8; ii++) {
        int m = m0 + ty * 8 + ii;
        int batch = m >> 10, l = m & 1023;
        #pragma unroll
        for (int jj = 0; jj < 8; jj++) {
            int n = n0 + tx + 16 * jj;
            float val = accv[ii][jj] + bias[n];
            int h = n / 192;
            int r = n - h * 192;
            int part = r >> 6, d = r & 63;
            float* dst = (part == 0) ? g_q : ((part == 1) ? g_k : g_v);
            dst[(((size_t)(batch * Hn + h)) * Ln + l) * DH + d] = val;
        }
    }
}

// ---------------- kernel 3: fused scores S = (QK^T + QE)/8 ------------------
// grid (16 ktiles, 16 qtiles, 32 bh); 256 threads; per tile:
//   C[64x192] = Q[64x64] * [K(64) | Ewindow(128)]^T  then band-combine.
#define SPAD 65
#define SCORES_SMEM (256 * SPAD * 4)   // 66560 bytes
__global__ __launch_bounds__(256) void scores_kernel() {
    extern __shared__ float sm[];
    float* Qs = sm;               // [64][SPAD]
    float* Bs = sm + 64 * SPAD;   // [192][SPAD] rows 0..63 = K, 64..191 = E window
    int kt = blockIdx.x, qt = blockIdx.y, bh = blockIdx.z;
    int q0 = qt * 64, k0 = kt * 64;
    const float* Qg = g_q + ((size_t)bh << 16);
    const float* Kg = g_k + ((size_t)bh << 16);
    int tid = threadIdx.x, tx = tid & 15, ty = tid >> 4;

    {
        int c = (tid & 15) * 4;
        #pragma unroll
        for (int p = 0; p < 4; p++) {
            int r = (tid >> 4) + p * 16;
            float4 v = *(const float4*)(Qg + (size_t)(q0 + r) * 64 + c);
            float* qd = Qs + r * SPAD + c;
            qd[0] = v.x; qd[1] = v.y; qd[2] = v.z; qd[3] = v.w;
            float4 w = *(const float4*)(Kg + (size_t)(k0 + r) * 64 + c);
            float* kd = Bs + r * SPAD + c;
            kd[0] = w.x; kd[1] = w.y; kd[2] = w.z; kd[3] = w.w;
        }
        int eb = q0 - k0 + 960;   // window base into emb rows (always in [0,1920])
        #pragma unroll
        for (int p = 0; p < 8; p++) {
            int t = (tid >> 4) + p * 16;
            float4 v = *(const float4*)(g_emb + (size_t)(eb + t) * 64 + c);
            float* ed = Bs + (64 + t) * SPAD + c;
            ed[0] = v.x; ed[1] = v.y; ed[2] = v.z; ed[3] = v.w;
        }
    }
    __syncthreads();

    float acc[4][12];
    #pragma unroll
    for (int i = 0; i < 4; i++)
        #pragma unroll
        for (int j = 0; j < 12; j++) acc[i][j] = 0.0f;

    #pragma unroll
    for (int kk = 0; kk < 64; kk++) {
        float a[4], b[12];
        #pragma unroll
        for (int ii = 0; ii < 4; ii++) a[ii] = Qs[(ty * 4 + ii) * SPAD + kk];
        #pragma unroll
        for (int cc = 0; cc < 12; cc++) b[cc] = Bs[(tx + 16 * cc) * SPAD + kk];
        #pragma unroll
        for (int ii = 0; ii < 4; ii++)
            #pragma unroll
            for (int cc = 0; cc < 12; cc++) acc[ii][cc] += a[ii] * b[cc];
    }
    __syncthreads();

    // stash R = Q·E^T part into smem (reuse buffer), then band-combine
    float* Rs = sm;   // [64][132]
    #pragma unroll
    for (int ii = 0; ii < 4; ii++)
        #pragma unroll
        for (int m = 0; m < 8; m++)
            Rs[(ty * 4 + ii) * 132 + tx + 16 * m] = acc[ii][4 + m];
    __syncthreads();

    float* Sg = g_S + ((size_t)bh << 20);
    #pragma unroll
    for (int ii = 0; ii < 4; ii++) {
        int i = ty * 4 + ii;
        #pragma unroll
        for (int jj = 0; jj < 4; jj++) {
            int j = tx + 16 * jj;
            float s = (acc[ii][jj] + Rs[i * 132 + (i - j + 63)]) * 0.125f;
            Sg[(size_t)(q0 + i) * 1024 + (k0 + j)] = s;
        }
    }
}

// ---------------- kernel 4: row softmax over S ------------------------------
__device__ __forceinline__ float warp_max(float v) {
    #pragma unroll
    for (int o = 16; o; o >>= 1) v = fmaxf(v, __shfl_xor_sync(0xffffffffu, v, o));
    return v;
}
__device__ __forceinline__ float warp_sum(float v) {
    #pragma unroll
    for (int o = 16; o; o >>= 1) v += __shfl_xor_sync(0xffffffffu, v, o);
    return v;
}

__global__ __launch_bounds__(128) void softmax_kernel() {
    float* p = g_S + (size_t)blockIdx.x * 1024;
    int tid = threadIdx.x;
    float4 a = ((const float4*)p)[tid];
    float4 b = ((const float4*)p)[tid + 128];
    float m = fmaxf(fmaxf(fmaxf(a.x, a.y), fmaxf(a.z, a.w)),
                    fmaxf(fmaxf(b.x, b.y), fmaxf(b.z, b.w)));
    m = warp_max(m);
    __shared__ float red[4];
    __shared__ float red2[4];
    if ((tid & 31) == 0) red[tid >> 5] = m;
    __syncthreads();
    m = fmaxf(fmaxf(red[0], red[1]), fmaxf(red[2], red[3]));
    a.x = expf(a.x - m); a.y = expf(a.y - m); a.z = expf(a.z - m); a.w = expf(a.w - m);
    b.x = expf(b.x - m); b.y = expf(b.y - m); b.z = expf(b.z - m); b.w = expf(b.w - m);
    float s = a.x + a.y + a.z + a.w + b.x + b.y + b.z + b.w;
    s = warp_sum(s);
    if ((tid & 31) == 0) red2[tid >> 5] = s;
    __syncthreads();
    s = red2[0] + red2[1] + red2[2] + red2[3];
    float inv = 1.0f / s;
    a.x *= inv; a.y *= inv; a.z *= inv; a.w *= inv;
    b.x *= inv; b.y *= inv; b.z *= inv; b.w *= inv;
    ((float4*)p)[tid] = a;
    ((float4*)p)[tid + 128] = b;
}

// ---------------- kernel 5: O = P@V with fused output transpose -------------
// grid (8 qtiles of 128, 32 bh); 256 threads; thread tile 8x4.
__global__ __launch_bounds__(256) void pv_kernel(float* __restrict__ out) {
    __shared__ float Ps[128 * 33];
    __shared__ float Vs[32 * 68];
    int qt = blockIdx.x;  // 0..7
    int bh = blockIdx.y;  // 0..31
    int q0 = qt * 128;
    const float* Pg = g_S + ((size_t)bh << 20) + (size_t)q0 * 1024;
    const float* Vg = g_v + ((size_t)bh << 16);
    int tid = threadIdx.x, tx = tid & 15, ty = tid >> 4;

    float acc[8][4];
    #pragma unroll
    for (int i = 0; i < 8; i++)
        #pragma unroll
        for (int j = 0; j < 4; j++) acc[i][j] = 0.0f;

    for (int kc = 0; kc < 1024; kc += 32) {
        #pragma unroll
        for (int p = 0; p < 4; p++) {
            int r = (tid >> 3) + p * 32;
            int c = (tid & 7) * 4;
            float4 v = *(const float4*)(Pg + (size_t)r * 1024 + kc + c);
            float* a = Ps + r * 33 + c;
            a[0] = v.x; a[1] = v.y; a[2] = v.z; a[3] = v.w;
        }
        #pragma unroll
        for (int p = 0; p < 2; p++) {
            int r = (tid >> 4) + p * 16;
            int c = (tid & 15) * 4;
            *(float4*)(Vs + r * 68 + c) = *(const float4*)(Vg + (size_t)(kc + r) * 64 + c);
        }
        __syncthreads();
        #pragma unroll
        for (int kk = 0; kk < 32; kk++) {
            float a[8], b[4];
            #pragma unroll
            for (int ii = 0; ii < 8; ii++) a[ii] = Ps[(ty * 8 + ii) * 33 + kk];
            #pragma unroll
            for (int cc = 0; cc < 4; cc++) b[cc] = Vs[kk * 68 + tx + 16 * cc];
            #pragma unroll
            for (int ii = 0; ii < 8; ii++)
                #pragma unroll
                for (int cc = 0; cc < 4; cc++) acc[ii][cc] += a[ii] * b[cc];
        }
        __syncthreads();
    }
    int batch = bh >> 3, h = bh & 7;
    #pragma unroll
    for (int ii = 0; ii < 8; ii++) {
        int l = q0 + ty * 8 + ii;
        #pragma unroll
        for (int cc = 0; cc < 4; cc++) {
            int d = tx + 16 * cc;
            out[((size_t)(batch * Ln + l)) * Dn + h * DH + d] = acc[ii][cc];
        }
    }
}

// ---------------- launch -----------------------------------------------------
extern "C" void kernel_launch(void* const* d_in, const int* in_sizes, int n_in,
                              void* d_out, int out_size) {
    (void)in_sizes; (void)n_in; (void)out_size;
    const float* x    = (const float*)d_in[0];
    const float* W    = (const float*)d_in[1];
    const float* bias = (const float*)d_in[2];
    float* out = (float*)d_out;

    cudaFuncSetAttribute(scores_kernel,
                         cudaFuncAttributeMaxDynamicSharedMemorySize, SCORES_SMEM);

    emb_kernel<<<EMB_ROWS, 32>>>();

    dim3 pg(12, 32);
    proj_kernel<<<pg, 256>>>(x, W, bias);

    dim3 sg(16, 16, BHn);
    scores_kernel<<<sg, 256, SCORES_SMEM>>>();

    softmax_kernel<<<BHn * Ln, 128>>>();

    dim3 vg(8, BHn);
    pv_kernel<<<vg, 256>>>(out);
}

// round 3
// speedup vs baseline: 2.1441x; 2.1441x over previous
#include <cuda_runtime.h>
#include <math.h>

#define Bn 4
#define Ln 1024
#define Dn 512
#define Hn 8
#define DH 64
#define BHn 32
#define EMB_ROWS 2047

// ---------------- scratch ----------------------------------------------------
__device__ float g_emb[2048 * 64];                 // row 2047 stays zero (never gathered)
__device__ float g_q[BHn * Ln * DH];
__device__ float g_k[BHn * Ln * DH];
__device__ float g_vt[BHn * DH * Ln];              // V transposed: [bh][d][kv]
__device__ float g_S[(size_t)BHn * Ln * Ln];

// ---------------- helpers ----------------------------------------------------
// cvt.rna.tf32.f32 requires a .b32 destination register in PTX.
__device__ __forceinline__ unsigned tf32b(float x) {
    unsigned y;
    asm("cvt.rna.tf32.f32 %0, %1;" : "=r"(y) : "f"(x));
    return y;
}
__device__ __forceinline__ float tf32r(float x) { return __uint_as_float(tf32b(x)); }
__device__ __forceinline__ unsigned fbits(float x) { return __float_as_uint(x); }

__device__ __forceinline__ void mma8(float* c, const unsigned* a, const unsigned* b) {
    asm volatile(
        "mma.sync.aligned.m16n8k8.row.col.f32.tf32.tf32.f32 "
        "{%0,%1,%2,%3}, {%4,%5,%6,%7}, {%8,%9}, {%0,%1,%2,%3};\n"
        : "+f"(c[0]), "+f"(c[1]), "+f"(c[2]), "+f"(c[3])
        : "r"(a[0]), "r"(a[1]), "r"(a[2]), "r"(a[3]), "r"(b[0]), "r"(b[1]));
}

// ---------------- kernel 1: sinusoidal embeddings ----------------------------
__global__ void emb_kernel() {
    int r = blockIdx.x;           // 0..2046
    int j = threadIdx.x;          // 0..31
    float pos = (float)(r - (Ln - 1));
    const float c = (float)(9.210340371976184 / 64.0);   // ln(10000)/64
    float div = expf(-(2.0f * (float)j) * c);
    float a = pos * div;
    g_emb[r * 64 + j]      = sinf(a);
    g_emb[r * 64 + 32 + j] = cosf(a);
}

// ---------------- kernel 2: proj GEMM (tf32 mma) -> Q,K,V^T scatter ----------
#define APAD 36     // 36 % 32 == 4 -> conflict-free A frag LDS
#define BPAD 136    // 136 % 32 == 8 -> conflict-free B frag LDS
__global__ __launch_bounds__(256) void proj_kernel(const float* __restrict__ x,
                                                   const float* __restrict__ W,
                                                   const float* __restrict__ bias) {
    __shared__ float As[128 * APAD];
    __shared__ float Bs[32 * BPAD];
    int bn = blockIdx.x;             // 0..11
    int bm = blockIdx.y;             // 0..31
    int m0 = bm * 128, n0 = bn * 128;
    int tid = threadIdx.x, lane = tid & 31, wid = tid >> 5;
    int wm = wid >> 1, wn = wid & 1;
    int g = lane >> 2, c4 = lane & 3;

    float acc[2][8][4];
    #pragma unroll
    for (int i = 0; i < 2; i++)
        #pragma unroll
        for (int j = 0; j < 8; j++)
            #pragma unroll
            for (int q = 0; q < 4; q++) acc[i][j][q] = 0.0f;

    for (int k0 = 0; k0 < 512; k0 += 32) {
        #pragma unroll
        for (int p = 0; p < 4; p++) {
            int r = (tid >> 3) + p * 32;
            int c = (tid & 7) * 4;
            float4 v = *(const float4*)(x + (size_t)(m0 + r) * 512 + k0 + c);
            float* a = As + r * APAD + c;
            a[0] = tf32r(v.x); a[1] = tf32r(v.y); a[2] = tf32r(v.z); a[3] = tf32r(v.w);
        }
        #pragma unroll
        for (int p = 0; p < 4; p++) {
            int r = (tid >> 5) + p * 8;
            int c = (tid & 31) * 4;
            float4 v = *(const float4*)(W + (size_t)(k0 + r) * 1536 + n0 + c);
            float* b = Bs + r * BPAD + c;
            b[0] = tf32r(v.x); b[1] = tf32r(v.y); b[2] = tf32r(v.z); b[3] = tf32r(v.w);
        }
        __syncthreads();
        #pragma unroll
        for (int ks = 0; ks < 4; ks++) {
            int kk = ks * 8;
            unsigned a[2][4];
            #pragma unroll
            for (int mi = 0; mi < 2; mi++) {
                int rb = wm * 32 + mi * 16 + g;
                a[mi][0] = fbits(As[rb * APAD + kk + c4]);
                a[mi][1] = fbits(As[(rb + 8) * APAD + kk + c4]);
                a[mi][2] = fbits(As[rb * APAD + kk + c4 + 4]);
                a[mi][3] = fbits(As[(rb + 8) * APAD + kk + c4 + 4]);
            }
            #pragma unroll
            for (int ni = 0; ni < 8; ni++) {
                int col = wn * 64 + ni * 8 + g;
                unsigned b[2];
                b[0] = fbits(Bs[(kk + c4) * BPAD + col]);
                b[1] = fbits(Bs[(kk + c4 + 4) * BPAD + col]);
                mma8(acc[0][ni], a[0], b);
                mma8(acc[1][ni], a[1], b);
            }
        }
        __syncthreads();
    }
    // epilogue: bias + scatter to Q / K / V^T
    #pragma unroll
    for (int mi = 0; mi < 2; mi++) {
        #pragma unroll
        for (int hh = 0; hh < 2; hh++) {
            int r = wm * 32 + mi * 16 + g + hh * 8;
            int mglob = m0 + r;
            int batch = mglob >> 10, l = mglob & 1023;
            #pragma unroll
            for (int ni = 0; ni < 8; ni++) {
                int n = n0 + wn * 64 + ni * 8 + c4 * 2;
                float v0 = acc[mi][ni][hh * 2 + 0] + bias[n];
                float v1 = acc[mi][ni][hh * 2 + 1] + bias[n + 1];
                int h = n / 192;
                int rr = n - h * 192;
                int part = rr >> 6, d = rr & 63;
                size_t bh = (size_t)(batch * Hn + h);
                if (part == 0) {
                    *(float2*)(g_q + (bh * Ln + l) * DH + d) = make_float2(v0, v1);
                } else if (part == 1) {
                    *(float2*)(g_k + (bh * Ln + l) * DH + d) = make_float2(v0, v1);
                } else {
                    g_vt[(bh * DH + d) * Ln + l]     = v0;
                    g_vt[(bh * DH + d + 1) * Ln + l] = v1;
                }
            }
        }
    }
}

// ---------------- kernel 3: fused scores (tf32 mma) --------------------------
// C[64x192] = Q[64x64] * [K(64) | Ewindow(128)]^T, then band combine.
#define SP 68                       // 68 % 32 == 4 -> conflict-free frag LDS
#define SCORES_SMEM ((64 + 192) * SP * 4)   // 69632 B
__global__ __launch_bounds__(256) void scores_kernel() {
    extern __shared__ float sm[];
    float* Qs  = sm;                // [64][SP]
    float* Bs2 = sm + 64 * SP;      // [192][SP]: rows 0..63 K, 64..191 E window
    int kt = blockIdx.x, qt = blockIdx.y, bh = blockIdx.z;
    int q0 = qt * 64, k0g = kt * 64;
    const float* Qg = g_q + ((size_t)bh << 16);
    const float* Kg = g_k + ((size_t)bh << 16);
    int tid = threadIdx.x, lane = tid & 31, wid = tid >> 5;
    int wm = wid >> 2, wn = wid & 3;    // 2 x 4 warp grid over 64 x 192
    int g = lane >> 2, c4 = lane & 3;

    {
        int c = (tid & 15) * 4;
        #pragma unroll
        for (int p = 0; p < 4; p++) {
            int r = (tid >> 4) + p * 16;
            float4 v = *(const float4*)(Qg + (size_t)(q0 + r) * 64 + c);
            float* qd = Qs + r * SP + c;
            qd[0] = tf32r(v.x); qd[1] = tf32r(v.y); qd[2] = tf32r(v.z); qd[3] = tf32r(v.w);
            float4 w = *(const float4*)(Kg + (size_t)(k0g + r) * 64 + c);
            float* kd = Bs2 + r * SP + c;
            kd[0] = tf32r(w.x); kd[1] = tf32r(w.y); kd[2] = tf32r(w.z); kd[3] = tf32r(w.w);
        }
        int eb = q0 - k0g + 960;    // [0, 1920]
        #pragma unroll
        for (int p = 0; p < 8; p++) {
            int t = (tid >> 4) + p * 16;
            float4 v = *(const float4*)(g_emb + (size_t)(eb + t) * 64 + c);
            float* ed = Bs2 + (64 + t) * SP + c;
            ed[0] = tf32r(v.x); ed[1] = tf32r(v.y); ed[2] = tf32r(v.z); ed[3] = tf32r(v.w);
        }
    }
    __syncthreads();

    float acc[2][6][4];
    #pragma unroll
    for (int i = 0; i < 2; i++)
        #pragma unroll
        for (int j = 0; j < 6; j++)
            #pragma unroll
            for (int q = 0; q < 4; q++) acc[i][j][q] = 0.0f;

    #pragma unroll
    for (int ks = 0; ks < 8; ks++) {
        int kk = ks * 8;
        unsigned a[2][4];
        #pragma unroll
        for (int mi = 0; mi < 2; mi++) {
            int rb = wm * 32 + mi * 16 + g;
            a[mi][0] = fbits(Qs[rb * SP + kk + c4]);
            a[mi][1] = fbits(Qs[(rb + 8) * SP + kk + c4]);
            a[mi][2] = fbits(Qs[rb * SP + kk + c4 + 4]);
            a[mi][3] = fbits(Qs[(rb + 8) * SP + kk + c4 + 4]);
        }
        #pragma unroll
        for (int ni = 0; ni < 6; ni++) {
            int col = wn * 48 + ni * 8 + g;
            unsigned b[2];
            b[0] = fbits(Bs2[col * SP + kk + c4]);
            b[1] = fbits(Bs2[col * SP + kk + c4 + 4]);
            mma8(acc[0][ni], a[0], b);
            mma8(acc[1][ni], a[1], b);
        }
    }
    __syncthreads();

    // stash R = Q.E^T (cols 64..191) into smem, then band-combine QK part
    float* Rs = sm;   // [64][132]
    #pragma unroll
    for (int mi = 0; mi < 2; mi++)
        #pragma unroll
        for (int ni = 0; ni < 6; ni++) {
            int cg = wn * 48 + ni * 8 + c4 * 2;
            if (cg >= 64) {
                #pragma unroll
                for (int hh = 0; hh < 2; hh++) {
                    int r = wm * 32 + mi * 16 + g + hh * 8;
                    *(float2*)(Rs + r * 132 + (cg - 64)) =
                        make_float2(acc[mi][ni][hh * 2], acc[mi][ni][hh * 2 + 1]);
                }
            }
        }
    __syncthreads();

    float* Sg = g_S + ((size_t)bh << 20);
    #pragma unroll
    for (int mi = 0; mi < 2; mi++)
        #pragma unroll
        for (int ni = 0; ni < 6; ni++) {
            int cg = wn * 48 + ni * 8 + c4 * 2;
            if (cg < 64) {
                #pragma unroll
                for (int hh = 0; hh < 2; hh++) {
                    int r = wm * 32 + mi * 16 + g + hh * 8;
                    float s0 = (acc[mi][ni][hh * 2]     + Rs[r * 132 + (r - cg + 63)]) * 0.125f;
                    float s1 = (acc[mi][ni][hh * 2 + 1] + Rs[r * 132 + (r - cg + 62)]) * 0.125f;
                    *(float2*)(Sg + (size_t)(q0 + r) * 1024 + k0g + cg) = make_float2(s0, s1);
                }
            }
        }
}

// ---------------- kernel 4: row softmax --------------------------------------
__device__ __forceinline__ float warp_max(float v) {
    #pragma unroll
    for (int o = 16; o; o >>= 1) v = fmaxf(v, __shfl_xor_sync(0xffffffffu, v, o));
    return v;
}
__device__ __forceinline__ float warp_sum(float v) {
    #pragma unroll
    for (int o = 16; o; o >>= 1) v += __shfl_xor_sync(0xffffffffu, v, o);
    return v;
}

__global__ __launch_bounds__(128) void softmax_kernel() {
    float* p = g_S + (size_t)blockIdx.x * 1024;
    int tid = threadIdx.x;
    float4 a = ((const float4*)p)[tid];
    float4 b = ((const float4*)p)[tid + 128];
    float m = fmaxf(fmaxf(fmaxf(a.x, a.y), fmaxf(a.z, a.w)),
                    fmaxf(fmaxf(b.x, b.y), fmaxf(b.z, b.w)));
    m = warp_max(m);
    __shared__ float red[4];
    __shared__ float red2[4];
    if ((tid & 31) == 0) red[tid >> 5] = m;
    __syncthreads();
    m = fmaxf(fmaxf(red[0], red[1]), fmaxf(red[2], red[3]));
    a.x = expf(a.x - m); a.y = expf(a.y - m); a.z = expf(a.z - m); a.w = expf(a.w - m);
    b.x = expf(b.x - m); b.y = expf(b.y - m); b.z = expf(b.z - m); b.w = expf(b.w - m);
    float s = a.x + a.y + a.z + a.w + b.x + b.y + b.z + b.w;
    s = warp_sum(s);
    if ((tid & 31) == 0) red2[tid >> 5] = s;
    __syncthreads();
    s = red2[0] + red2[1] + red2[2] + red2[3];
    float inv = 1.0f / s;
    a.x *= inv; a.y *= inv; a.z *= inv; a.w *= inv;
    b.x *= inv; b.y *= inv; b.z *= inv; b.w *= inv;
    ((float4*)p)[tid] = a;
    ((float4*)p)[tid + 128] = b;
}

// ---------------- kernel 5: O = P@V (split-tf32 P for accuracy) --------------
#define PPAD 36
__global__ __launch_bounds__(256) void pv_kernel(float* __restrict__ out) {
    __shared__ float Ph[128 * PPAD];
    __shared__ float Pl[128 * PPAD];
    __shared__ float Vs[64 * PPAD];
    int qt = blockIdx.x;   // 0..7
    int bh = blockIdx.y;   // 0..31
    int q0 = qt * 128;
    const float* Pg = g_S + ((size_t)bh << 20) + (size_t)q0 * 1024;
    const float* Vg = g_vt + ((size_t)bh << 16);
    int tid = threadIdx.x, lane = tid & 31, wid = tid >> 5;
    int wm = wid >> 1, wn = wid & 1;
    int g = lane >> 2, c4 = lane & 3;

    float acc[2][4][4];
    #pragma unroll
    for (int i = 0; i < 2; i++)
        #pragma unroll
        for (int j = 0; j < 4; j++)
            #pragma unroll
            for (int q = 0; q < 4; q++) acc[i][j][q] = 0.0f;

    for (int kc = 0; kc < 1024; kc += 32) {
        #pragma unroll
        for (int p = 0; p < 4; p++) {
            int r = (tid >> 3) + p * 32;
            int c = (tid & 7) * 4;
            float4 v = *(const float4*)(Pg + (size_t)r * 1024 + kc + c);
            float h0 = tf32r(v.x), h1 = tf32r(v.y), h2 = tf32r(v.z), h3 = tf32r(v.w);
            float* dh = Ph + r * PPAD + c;
            float* dl = Pl + r * PPAD + c;
            dh[0] = h0; dh[1] = h1; dh[2] = h2; dh[3] = h3;
            dl[0] = tf32r(v.x - h0); dl[1] = tf32r(v.y - h1);
            dl[2] = tf32r(v.z - h2); dl[3] = tf32r(v.w - h3);
        }
        {
            int d = tid >> 2;
            int cb = (tid & 3) * 8;
            const float* src = Vg + (size_t)d * 1024 + kc + cb;
            float4 v0 = *(const float4*)(src);
            float4 v1 = *(const float4*)(src + 4);
            float* dv = Vs + d * PPAD + cb;
            dv[0] = tf32r(v0.x); dv[1] = tf32r(v0.y); dv[2] = tf32r(v0.z); dv[3] = tf32r(v0.w);
            dv[4] = tf32r(v1.x); dv[5] = tf32r(v1.y); dv[6] = tf32r(v1.z); dv[7] = tf32r(v1.w);
        }
        __syncthreads();
        #pragma unroll
        for (int ks = 0; ks < 4; ks++) {
            int kk = ks * 8;
            unsigned ah[2][4], al[2][4];
            #pragma unroll
            for (int mi = 0; mi < 2; mi++) {
                int rb = wm * 32 + mi * 16 + g;
                ah[mi][0] = fbits(Ph[rb * PPAD + kk + c4]);
                ah[mi][1] = fbits(Ph[(rb + 8) * PPAD + kk + c4]);
                ah[mi][2] = fbits(Ph[rb * PPAD + kk + c4 + 4]);
                ah[mi][3] = fbits(Ph[(rb + 8) * PPAD + kk + c4 + 4]);
                al[mi][0] = fbits(Pl[rb * PPAD + kk + c4]);
                al[mi][1] = fbits(Pl[(rb + 8) * PPAD + kk + c4]);
                al[mi][2] = fbits(Pl[rb * PPAD + kk + c4 + 4]);
                al[mi][3] = fbits(Pl[(rb + 8) * PPAD + kk + c4 + 4]);
            }
            #pragma unroll
            for (int ni = 0; ni < 4; ni++) {
                int col = wn * 32 + ni * 8 + g;
                unsigned b[2];
                b[0] = fbits(Vs[col * PPAD + kk + c4]);
                b[1] = fbits(Vs[col * PPAD + kk + c4 + 4]);
                mma8(acc[0][ni], ah[0], b);
                mma8(acc[1][ni], ah[1], b);
                mma8(acc[0][ni], al[0], b);
                mma8(acc[1][ni], al[1], b);
            }
        }
        __syncthreads();
    }
    int batch = bh >> 3, h = bh & 7;
    #pragma unroll
    for (int mi = 0; mi < 2; mi++)
        #pragma unroll
        for (int hh = 0; hh < 2; hh++) {
            int l = q0 + wm * 32 + mi * 16 + g + hh * 8;
            #pragma unroll
            for (int ni = 0; ni < 4; ni++) {
                int d = wn * 32 + ni * 8 + c4 * 2;
                *(float2*)(out + ((size_t)(batch * Ln + l)) * Dn + h * DH + d) =
                    make_float2(acc[mi][ni][hh * 2], acc[mi][ni][hh * 2 + 1]);
            }
        }
}

// ---------------- launch ------------------------------------------------------
extern "C" void kernel_launch(void* const* d_in, const int* in_sizes, int n_in,
                              void* d_out, int out_size) {
    (void)in_sizes; (void)n_in; (void)out_size;
    const float* x    = (const float*)d_in[0];
    const float* W    = (const float*)d_in[1];
    const float* bias = (const float*)d_in[2];
    float* out = (float*)d_out;

    cudaFuncSetAttribute(scores_kernel,
                         cudaFuncAttributeMaxDynamicSharedMemorySize, SCORES_SMEM);

    emb_kernel<<<EMB_ROWS, 32>>>();

    dim3 pg(12, 32);
    proj_kernel<<<pg, 256>>>(x, W, bias);

    dim3 sg(16, 16, BHn);
    scores_kernel<<<sg, 256, SCORES_SMEM>>>();

    softmax_kernel<<<BHn * Ln, 128>>>();

    dim3 vg(8, BHn);
    pv_kernel<<<vg, 256>>>(out);
}

// round 4
// speedup vs baseline: 2.5454x; 1.1872x over previous
#include <cuda_runtime.h>
#include <math.h>

#define Bn 4
#define Ln 1024
#define Dn 512
#define Hn 8
#define DH 64
#define BHn 32

// ---------------- scratch ----------------------------------------------------
__device__ float g_q[BHn * Ln * DH];
__device__ float g_k[BHn * Ln * DH];
__device__ float g_vt[BHn * DH * Ln];     // V transposed: [bh][d][kv]
__device__ float g_kp[Ln * DH];           // K' [k][0:32]=cos(k*w), [32:64]=sin(k*w)

// ---------------- helpers ----------------------------------------------------
__device__ __forceinline__ unsigned tf32b(float x) {
    unsigned y;
    asm("cvt.rna.tf32.f32 %0, %1;" : "=r"(y) : "f"(x));
    return y;
}
__device__ __forceinline__ float tf32r(float x) { return __uint_as_float(tf32b(x)); }
__device__ __forceinline__ unsigned fbits(float x) { return __float_as_uint(x); }

__device__ __forceinline__ void mma8(float* c, const unsigned* a, const unsigned* b) {
    asm volatile(
        "mma.sync.aligned.m16n8k8.row.col.f32.tf32.tf32.f32 "
        "{%0,%1,%2,%3}, {%4,%5,%6,%7}, {%8,%9}, {%0,%1,%2,%3};\n"
        : "+f"(c[0]), "+f"(c[1]), "+f"(c[2]), "+f"(c[3])
        : "r"(a[0]), "r"(a[1]), "r"(a[2]), "r"(a[3]), "r"(b[0]), "r"(b[1]));
}

// ---------------- kernel 1: K' table (data independent) -----------------------
// w_j = exp(-(2j) * ln(10000)/64); K'[k][j] = cos(k*w_j), K'[k][32+j] = sin(k*w_j)
__global__ void kp_kernel() {
    int k = blockIdx.x;           // 0..1023
    int j = threadIdx.x;          // 0..31
    float w = expf(-(float)(2 * j) * 0.14391157f);
    float s, c;
    sincosf((float)k * w, &s, &c);
    g_kp[k * 64 + j]      = c;
    g_kp[k * 64 + 32 + j] = s;
}

// ---------------- kernel 2: proj GEMM (tf32 mma) -> Q,K,V^T scatter ----------
#define APAD 36     // %32==4 -> conflict-free A frag LDS ([m][k] layout)
#define BPAD 136    // %32==8 -> conflict-free B frag LDS ([k][n] layout)
__global__ __launch_bounds__(256) void proj_kernel(const float* __restrict__ x,
                                                   const float* __restrict__ W,
                                                   const float* __restrict__ bias) {
    __shared__ float As[128 * APAD];
    __shared__ float Bs[32 * BPAD];
    int bn = blockIdx.x;             // 0..11
    int bm = blockIdx.y;             // 0..31
    int m0 = bm * 128, n0 = bn * 128;
    int tid = threadIdx.x, lane = tid & 31, wid = tid >> 5;
    int wm = wid >> 1, wn = wid & 1;
    int g = lane >> 2, c4 = lane & 3;

    float acc[2][8][4];
    #pragma unroll
    for (int i = 0; i < 2; i++)
        #pragma unroll
        for (int j = 0; j < 8; j++)
            #pragma unroll
            for (int q = 0; q < 4; q++) acc[i][j][q] = 0.0f;

    for (int k0 = 0; k0 < 512; k0 += 32) {
        #pragma unroll
        for (int p = 0; p < 4; p++) {
            int r = (tid >> 3) + p * 32;
            int c = (tid & 7) * 4;
            float4 v = *(const float4*)(x + (size_t)(m0 + r) * 512 + k0 + c);
            float* a = As + r * APAD + c;
            a[0] = tf32r(v.x); a[1] = tf32r(v.y); a[2] = tf32r(v.z); a[3] = tf32r(v.w);
        }
        #pragma unroll
        for (int p = 0; p < 4; p++) {
            int r = (tid >> 5) + p * 8;
            int c = (tid & 31) * 4;
            float4 v = *(const float4*)(W + (size_t)(k0 + r) * 1536 + n0 + c);
            float* b = Bs + r * BPAD + c;
            b[0] = tf32r(v.x); b[1] = tf32r(v.y); b[2] = tf32r(v.z); b[3] = tf32r(v.w);
        }
        __syncthreads();
        #pragma unroll
        for (int ks = 0; ks < 4; ks++) {
            int kk = ks * 8;
            unsigned a[2][4];
            #pragma unroll
            for (int mi = 0; mi < 2; mi++) {
                int rb = wm * 32 + mi * 16 + g;
                a[mi][0] = fbits(As[rb * APAD + kk + c4]);
                a[mi][1] = fbits(As[(rb + 8) * APAD + kk + c4]);
                a[mi][2] = fbits(As[rb * APAD + kk + c4 + 4]);
                a[mi][3] = fbits(As[(rb + 8) * APAD + kk + c4 + 4]);
            }
            #pragma unroll
            for (int ni = 0; ni < 8; ni++) {
                int col = wn * 64 + ni * 8 + g;
                unsigned b[2];
                b[0] = fbits(Bs[(kk + c4) * BPAD + col]);
                b[1] = fbits(Bs[(kk + c4 + 4) * BPAD + col]);
                mma8(acc[0][ni], a[0], b);
                mma8(acc[1][ni], a[1], b);
            }
        }
        __syncthreads();
    }
    // epilogue: bias + scatter to Q / K / V^T
    #pragma unroll
    for (int mi = 0; mi < 2; mi++) {
        #pragma unroll
        for (int hh = 0; hh < 2; hh++) {
            int r = wm * 32 + mi * 16 + g + hh * 8;
            int mglob = m0 + r;
            int batch = mglob >> 10, l = mglob & 1023;
            #pragma unroll
            for (int ni = 0; ni < 8; ni++) {
                int n = n0 + wn * 64 + ni * 8 + c4 * 2;
                float v0 = acc[mi][ni][hh * 2 + 0] + bias[n];
                float v1 = acc[mi][ni][hh * 2 + 1] + bias[n + 1];
                int h = n / 192;
                int rr = n - h * 192;
                int part = rr >> 6, d = rr & 63;
                size_t bh = (size_t)(batch * Hn + h);
                if (part == 0) {
                    *(float2*)(g_q + (bh * Ln + l) * DH + d) = make_float2(v0, v1);
                } else if (part == 1) {
                    *(float2*)(g_k + (bh * Ln + l) * DH + d) = make_float2(v0, v1);
                } else {
                    g_vt[(bh * DH + d) * Ln + l]     = v0;
                    g_vt[(bh * DH + d + 1) * Ln + l] = v1;
                }
            }
        }
    }
}

// ---------------- kernel 3: fused attention (flash-style) --------------------
// Per (bh, 64-row q-tile): loop 16 kv tiles of 64.
//   S[64x64] = [Q|Q'] . [K|K']^T (k=128), P = exp(S), l += rowsum(P),
//   O += P @ V (split-tf32 P). Final O/l with fused transpose to out.
#define QP 132      // [n][k] pad, %32==4 -> conflict-free frags
#define VP 68       // %32==4
#define SM_QS 0
#define SM_BS (64 * QP)
#define SM_VS (2 * 64 * QP)
#define SM_PS (2 * 64 * QP + 64 * VP)
#define SM_L  (2 * 64 * QP + 2 * 64 * VP)
#define ATT_SMEM ((2 * 64 * QP + 2 * 64 * VP + 64) * 4)   // 102656 B

__global__ __launch_bounds__(256) void attn_kernel(float* __restrict__ out) {
    extern __shared__ float sm[];
    float* Qs   = sm + SM_QS;   // [64 rows][128 k + pad]  (Q | Q')
    float* Bs   = sm + SM_BS;   // [64 n(kv)][128 k + pad] (K | K')
    float* Vs   = sm + SM_VS;   // [64 n(d)][64 k(kv) + pad] (V^T)
    float* Ps   = sm + SM_PS;   // [64 rows][64 kv + pad]
    float* lrow = sm + SM_L;    // [64] row sums
    int qt = blockIdx.x, bh = blockIdx.y;
    int q0 = qt * 64;
    const float* Qg = g_q  + ((size_t)bh << 16);
    const float* Kg = g_k  + ((size_t)bh << 16);
    const float* Vg = g_vt + ((size_t)bh << 16);
    int tid = threadIdx.x, lane = tid & 31, wid = tid >> 5;
    int wm = wid >> 1, wn = wid & 1;     // 4 x 2 warps over 64x64 output
    int g = lane >> 2, c4 = lane & 3;

    // ---- load Q tile, build Q' via trig identity, scale by 1/8, tf32 ----
    {
        int r = tid >> 2;                 // 0..63
        int qq = (tid & 3) * 8;           // j base: 0,8,16,24
        const float* src = Qg + (size_t)(q0 + r) * 64;
        float qa[8], qb[8];
        #pragma unroll
        for (int i = 0; i < 8; i += 4) {
            float4 v = *(const float4*)(src + qq + i);
            qa[i] = v.x; qa[i+1] = v.y; qa[i+2] = v.z; qa[i+3] = v.w;
            float4 u = *(const float4*)(src + 32 + qq + i);
            qb[i] = u.x; qb[i+1] = u.y; qb[i+2] = u.z; qb[i+3] = u.w;
        }
        float pos = (float)(q0 + r);
        float* qrow = Qs + r * QP;
        #pragma unroll
        for (int i = 0; i < 8; i++) {
            int j = qq + i;
            float w = expf(-(float)(2 * j) * 0.14391157f);
            float s, c;
            sincosf(pos * w, &s, &c);
            qrow[j]      = tf32r(0.125f * qa[i]);
            qrow[j + 32] = tf32r(0.125f * qb[i]);
            qrow[j + 64] = tf32r(0.125f * (qa[i] * s + qb[i] * c));
            qrow[j + 96] = tf32r(0.125f * (qb[i] * s - qa[i] * c));
        }
        if (tid < 64) lrow[tid] = 0.0f;
    }

    float acco[4][4];
    #pragma unroll
    for (int i = 0; i < 4; i++)
        #pragma unroll
        for (int q = 0; q < 4; q++) acco[i][q] = 0.0f;

    __syncthreads();

    for (int kt = 0; kt < 16; kt++) {
        int k0 = kt * 64;
        // ---- stage K|K' and V^T tiles ----
        {
            int r = tid >> 2;
            int cc = (tid & 3) * 16;
            const float* ksrc = Kg + (size_t)(k0 + r) * 64 + cc;
            const float* psrc = g_kp + (size_t)(k0 + r) * 64 + cc;
            float* brow = Bs + r * QP;
            #pragma unroll
            for (int i = 0; i < 16; i += 4) {
                float4 v = *(const float4*)(ksrc + i);
                brow[cc + i]     = tf32r(v.x); brow[cc + i + 1] = tf32r(v.y);
                brow[cc + i + 2] = tf32r(v.z); brow[cc + i + 3] = tf32r(v.w);
                float4 u = *(const float4*)(psrc + i);
                brow[64 + cc + i]     = tf32r(u.x); brow[64 + cc + i + 1] = tf32r(u.y);
                brow[64 + cc + i + 2] = tf32r(u.z); brow[64 + cc + i + 3] = tf32r(u.w);
            }
            const float* vsrc = Vg + (size_t)r * Ln + k0 + cc;   // r = d index
            float* vrow = Vs + r * VP;
            #pragma unroll
            for (int i = 0; i < 16; i += 4) {
                float4 v = *(const float4*)(vsrc + i);
                vrow[cc + i]     = tf32r(v.x); vrow[cc + i + 1] = tf32r(v.y);
                vrow[cc + i + 2] = tf32r(v.z); vrow[cc + i + 3] = tf32r(v.w);
            }
        }
        __syncthreads();

        // ---- S = [Q|Q'] . [K|K']^T  (64x64, k=128) ----
        float accs[4][4];
        #pragma unroll
        for (int i = 0; i < 4; i++)
            #pragma unroll
            for (int q = 0; q < 4; q++) accs[i][q] = 0.0f;
        int rb = wm * 16 + g;
        #pragma unroll
        for (int ks = 0; ks < 16; ks++) {
            int kk = ks * 8;
            unsigned a[4];
            a[0] = fbits(Qs[rb * QP + kk + c4]);
            a[1] = fbits(Qs[(rb + 8) * QP + kk + c4]);
            a[2] = fbits(Qs[rb * QP + kk + c4 + 4]);
            a[3] = fbits(Qs[(rb + 8) * QP + kk + c4 + 4]);
            #pragma unroll
            for (int ni = 0; ni < 4; ni++) {
                int col = wn * 32 + ni * 8 + g;
                unsigned b[2];
                b[0] = fbits(Bs[col * QP + kk + c4]);
                b[1] = fbits(Bs[col * QP + kk + c4 + 4]);
                mma8(accs[ni], a, b);
            }
        }

        // ---- P = exp(S); write to smem; accumulate row sums ----
        #pragma unroll
        for (int hh = 0; hh < 2; hh++) {
            int r = wm * 16 + g + hh * 8;
            float part = 0.0f;
            #pragma unroll
            for (int ni = 0; ni < 4; ni++) {
                float p0 = __expf(accs[ni][hh * 2 + 0]);
                float p1 = __expf(accs[ni][hh * 2 + 1]);
                part += p0 + p1;
                int col = wn * 32 + ni * 8 + c4 * 2;
                *(float2*)(Ps + r * VP + col) = make_float2(p0, p1);
            }
            part += __shfl_xor_sync(0xffffffffu, part, 1);
            part += __shfl_xor_sync(0xffffffffu, part, 2);
            if (c4 == 0) atomicAdd(&lrow[r], part);
        }
        __syncthreads();

        // ---- O += P @ V  (split-tf32 P) ----
        #pragma unroll
        for (int ks = 0; ks < 8; ks++) {
            int kk = ks * 8;
            float p0 = Ps[rb * VP + kk + c4];
            float p1 = Ps[(rb + 8) * VP + kk + c4];
            float p2 = Ps[rb * VP + kk + c4 + 4];
            float p3 = Ps[(rb + 8) * VP + kk + c4 + 4];
            unsigned ah[4] = { tf32b(p0), tf32b(p1), tf32b(p2), tf32b(p3) };
            unsigned al[4] = { tf32b(p0 - __uint_as_float(ah[0])),
                               tf32b(p1 - __uint_as_float(ah[1])),
                               tf32b(p2 - __uint_as_float(ah[2])),
                               tf32b(p3 - __uint_as_float(ah[3])) };
            #pragma unroll
            for (int ni = 0; ni < 4; ni++) {
                int col = wn * 32 + ni * 8 + g;
                unsigned b[2];
                b[0] = fbits(Vs[col * VP + kk + c4]);
                b[1] = fbits(Vs[col * VP + kk + c4 + 4]);
                mma8(acco[ni], ah, b);
                mma8(acco[ni], al, b);
            }
        }
        __syncthreads();
    }

    // ---- epilogue: O / l, fused transpose to [B, L, D] ----
    int batch = bh >> 3, h = bh & 7;
    #pragma unroll
    for (int hh = 0; hh < 2; hh++) {
        int r = wm * 16 + g + hh * 8;
        float inv = 1.0f / lrow[r];
        int l = q0 + r;
        #pragma unroll
        for (int ni = 0; ni < 4; ni++) {
            int d = wn * 32 + ni * 8 + c4 * 2;
            *(float2*)(out + ((size_t)(batch * Ln + l)) * Dn + h * DH + d) =
                make_float2(acco[ni][hh * 2] * inv, acco[ni][hh * 2 + 1] * inv);
        }
    }
}

// ---------------- launch ------------------------------------------------------
extern "C" void kernel_launch(void* const* d_in, const int* in_sizes, int n_in,
                              void* d_out, int out_size) {
    (void)in_sizes; (void)n_in; (void)out_size;
    const float* x    = (const float*)d_in[0];
    const float* W    = (const float*)d_in[1];
    const float* bias = (const float*)d_in[2];
    float* out = (float*)d_out;

    cudaFuncSetAttribute(attn_kernel,
                         cudaFuncAttributeMaxDynamicSharedMemorySize, ATT_SMEM);

    kp_kernel<<<Ln, 32>>>();

    dim3 pg(12, 32);
    proj_kernel<<<pg, 256>>>(x, W, bias);

    dim3 ag(16, BHn);
    attn_kernel<<<ag, 256, ATT_SMEM>>>(out);
}

// round 5
// speedup vs baseline: 2.9702x; 1.1669x over previous
#include <cuda_runtime.h>
#include <math.h>

#define Bn 4
#define Ln 1024
#define Dn 512
#define Hn 8
#define DH 64
#define BHn 32

// ---------------- scratch ----------------------------------------------------
__device__ float g_q[BHn * Ln * DH];      // full fp32 (Q' build needs precision)
__device__ float g_k[BHn * Ln * DH];      // tf32-pre-rounded
__device__ float g_vt[BHn * DH * Ln];     // V transposed [bh][d][kv], tf32-pre-rounded
__device__ float g_kp[Ln * DH];           // K' [k][0:32]=cos(kw),[32:64]=sin(kw), tf32

// ---------------- helpers ----------------------------------------------------
__device__ __forceinline__ unsigned tf32b(float x) {
    unsigned y;
    asm("cvt.rna.tf32.f32 %0, %1;" : "=r"(y) : "f"(x));
    return y;
}
__device__ __forceinline__ float tf32r(float x) { return __uint_as_float(tf32b(x)); }
__device__ __forceinline__ unsigned fbits(float x) { return __float_as_uint(x); }

__device__ __forceinline__ void mma8(float* c, const unsigned* a, const unsigned* b) {
    asm volatile(
        "mma.sync.aligned.m16n8k8.row.col.f32.tf32.tf32.f32 "
        "{%0,%1,%2,%3}, {%4,%5,%6,%7}, {%8,%9}, {%0,%1,%2,%3};\n"
        : "+f"(c[0]), "+f"(c[1]), "+f"(c[2]), "+f"(c[3])
        : "r"(a[0]), "r"(a[1]), "r"(a[2]), "r"(a[3]), "r"(b[0]), "r"(b[1]));
}

__device__ __forceinline__ void cpa16(unsigned dst, const float* src) {
    asm volatile("cp.async.cg.shared.global [%0], [%1], 16;\n" :: "r"(dst), "l"(src));
}

// ---------------- kernel 1: K' table (tf32 pre-rounded) ----------------------
__global__ void kp_kernel() {
    int k = blockIdx.x;           // 0..1023
    int j = threadIdx.x;          // 0..31
    float w = expf(-(float)(2 * j) * 0.14391157f);
    float s, c;
    sincosf((float)k * w, &s, &c);
    g_kp[k * 64 + j]      = tf32r(c);
    g_kp[k * 64 + 32 + j] = tf32r(s);
}

// ---------------- kernel 2: proj GEMM (tf32 mma) -> Q,K,V^T scatter ----------
#define APAD 36
#define BPAD 136
__global__ __launch_bounds__(256) void proj_kernel(const float* __restrict__ x,
                                                   const float* __restrict__ W,
                                                   const float* __restrict__ bias) {
    __shared__ float As[128 * APAD];
    __shared__ float Bs[32 * BPAD];
    int bn = blockIdx.x;             // 0..11
    int bm = blockIdx.y;             // 0..31
    int m0 = bm * 128, n0 = bn * 128;
    int tid = threadIdx.x, lane = tid & 31, wid = tid >> 5;
    int wm = wid >> 1, wn = wid & 1;
    int g = lane >> 2, c4 = lane & 3;

    float acc[2][8][4];
    #pragma unroll
    for (int i = 0; i < 2; i++)
        #pragma unroll
        for (int j = 0; j < 8; j++)
            #pragma unroll
            for (int q = 0; q < 4; q++) acc[i][j][q] = 0.0f;

    for (int k0 = 0; k0 < 512; k0 += 32) {
        #pragma unroll
        for (int p = 0; p < 4; p++) {
            int r = (tid >> 3) + p * 32;
            int c = (tid & 7) * 4;
            float4 v = *(const float4*)(x + (size_t)(m0 + r) * 512 + k0 + c);
            float* a = As + r * APAD + c;
            a[0] = tf32r(v.x); a[1] = tf32r(v.y); a[2] = tf32r(v.z); a[3] = tf32r(v.w);
        }
        #pragma unroll
        for (int p = 0; p < 4; p++) {
            int r = (tid >> 5) + p * 8;
            int c = (tid & 31) * 4;
            float4 v = *(const float4*)(W + (size_t)(k0 + r) * 1536 + n0 + c);
            float* b = Bs + r * BPAD + c;
            b[0] = tf32r(v.x); b[1] = tf32r(v.y); b[2] = tf32r(v.z); b[3] = tf32r(v.w);
        }
        __syncthreads();
        #pragma unroll
        for (int ks = 0; ks < 4; ks++) {
            int kk = ks * 8;
            unsigned a[2][4];
            #pragma unroll
            for (int mi = 0; mi < 2; mi++) {
                int rb = wm * 32 + mi * 16 + g;
                a[mi][0] = fbits(As[rb * APAD + kk + c4]);
                a[mi][1] = fbits(As[(rb + 8) * APAD + kk + c4]);
                a[mi][2] = fbits(As[rb * APAD + kk + c4 + 4]);
                a[mi][3] = fbits(As[(rb + 8) * APAD + kk + c4 + 4]);
            }
            #pragma unroll
            for (int ni = 0; ni < 8; ni++) {
                int col = wn * 64 + ni * 8 + g;
                unsigned b[2];
                b[0] = fbits(Bs[(kk + c4) * BPAD + col]);
                b[1] = fbits(Bs[(kk + c4 + 4) * BPAD + col]);
                mma8(acc[0][ni], a[0], b);
                mma8(acc[1][ni], a[1], b);
            }
        }
        __syncthreads();
    }
    // epilogue: bias + scatter; K and V^T stored tf32-pre-rounded
    #pragma unroll
    for (int mi = 0; mi < 2; mi++) {
        #pragma unroll
        for (int hh = 0; hh < 2; hh++) {
            int r = wm * 32 + mi * 16 + g + hh * 8;
            int mglob = m0 + r;
            int batch = mglob >> 10, l = mglob & 1023;
            #pragma unroll
            for (int ni = 0; ni < 8; ni++) {
                int n = n0 + wn * 64 + ni * 8 + c4 * 2;
                float v0 = acc[mi][ni][hh * 2 + 0] + bias[n];
                float v1 = acc[mi][ni][hh * 2 + 1] + bias[n + 1];
                int h = n / 192;
                int rr = n - h * 192;
                int part = rr >> 6, d = rr & 63;
                size_t bh = (size_t)(batch * Hn + h);
                if (part == 0) {
                    *(float2*)(g_q + (bh * Ln + l) * DH + d) = make_float2(v0, v1);
                } else if (part == 1) {
                    *(float2*)(g_k + (bh * Ln + l) * DH + d) =
                        make_float2(tf32r(v0), tf32r(v1));
                } else {
                    g_vt[(bh * DH + d) * Ln + l]     = tf32r(v0);
                    g_vt[(bh * DH + d + 1) * Ln + l] = tf32r(v1);
                }
            }
        }
    }
}

// ---------------- kernel 3: fused attention, cp.async double-buffered --------
#define QP 132      // pad %32==4 -> conflict-free frag LDS; row = 528B (16B mult)
#define VP 68       // pad %32==4; row = 272B (16B mult)
#define SM_B  (64 * QP)                        // B stage 0 (stage 1 at +64*QP)
#define SM_V  (3 * 64 * QP)                    // V stage 0 (stage 1 at +64*VP)
#define SM_PS (3 * 64 * QP + 2 * 64 * VP)
#define SM_L  (SM_PS + 64 * VP)
#define ATT_SMEM ((SM_L + 64) * 4)             // 153856 B

// prefetch one kv tile: K|K' -> B stage, V^T -> V stage (16B cp.async)
__device__ __forceinline__ void stage_tile(float* Bdst, float* Vdst,
                                           const float* Kg, const float* Vg,
                                           int k0, int tid) {
    unsigned bB = (unsigned)__cvta_generic_to_shared(Bdst);
    unsigned bV = (unsigned)__cvta_generic_to_shared(Vdst);
    #pragma unroll
    for (int p = 0; p < 8; p++) {
        int id = p * 256 + tid;       // 0..2047, 32 chunks/row
        int r = id >> 5;
        int c = id & 31;
        const float* src = (c < 16) ? (Kg + (size_t)(k0 + r) * 64 + c * 4)
                                    : (g_kp + (size_t)(k0 + r) * 64 + (c - 16) * 4);
        cpa16(bB + (unsigned)(r * QP + c * 4) * 4, src);
    }
    #pragma unroll
    for (int p = 0; p < 4; p++) {
        int id = p * 256 + tid;       // 0..1023, 16 chunks/row
        int r = id >> 4;
        int c = id & 15;
        cpa16(bV + (unsigned)(r * VP + c * 4) * 4, Vg + (size_t)r * Ln + k0 + c * 4);
    }
}

__global__ __launch_bounds__(256, 1) void attn_kernel(float* __restrict__ out) {
    extern __shared__ float sm[];
    float* Qs   = sm;            // [64][QP]  (Q | Q'), tf32, scaled 1/8
    float* Bs   = sm + SM_B;     // 2 x [64][QP]  (K | K')
    float* Vs   = sm + SM_V;     // 2 x [64][VP]  (V^T)
    float* Ps   = sm + SM_PS;    // [64][VP]
    float* lrow = sm + SM_L;     // [64]
    int qt = blockIdx.x, bh = blockIdx.y;
    int q0 = qt * 64;
    const float* Qg = g_q  + ((size_t)bh << 16);
    const float* Kg = g_k  + ((size_t)bh << 16);
    const float* Vg = g_vt + ((size_t)bh << 16);
    int tid = threadIdx.x, lane = tid & 31, wid = tid >> 5;
    int wm = wid >> 1, wn = wid & 1;     // 4 x 2 warps over 64x64
    int g = lane >> 2, c4 = lane & 3;

    // prologue: prefetch tile 0 while building Q|Q'
    stage_tile(Bs, Vs, Kg, Vg, 0, tid);
    asm volatile("cp.async.commit_group;\n");

    {
        int r = tid >> 2;                 // 0..63
        int qq = (tid & 3) * 8;
        const float* src = Qg + (size_t)(q0 + r) * 64;
        float qa[8], qb[8];
        #pragma unroll
        for (int i = 0; i < 8; i += 4) {
            float4 v = *(const float4*)(src + qq + i);
            qa[i] = v.x; qa[i+1] = v.y; qa[i+2] = v.z; qa[i+3] = v.w;
            float4 u = *(const float4*)(src + 32 + qq + i);
            qb[i] = u.x; qb[i+1] = u.y; qb[i+2] = u.z; qb[i+3] = u.w;
        }
        float pos = (float)(q0 + r);
        float* qrow = Qs + r * QP;
        #pragma unroll
        for (int i = 0; i < 8; i++) {
            int j = qq + i;
            float w = expf(-(float)(2 * j) * 0.14391157f);
            float s, c;
            sincosf(pos * w, &s, &c);
            qrow[j]      = tf32r(0.125f * qa[i]);
            qrow[j + 32] = tf32r(0.125f * qb[i]);
            qrow[j + 64] = tf32r(0.125f * (qa[i] * s + qb[i] * c));
            qrow[j + 96] = tf32r(0.125f * (qb[i] * s - qa[i] * c));
        }
        if (tid < 64) lrow[tid] = 0.0f;
    }

    float acco[4][4];
    #pragma unroll
    for (int i = 0; i < 4; i++)
        #pragma unroll
        for (int q = 0; q < 4; q++) acco[i][q] = 0.0f;

    int rb = wm * 16 + g;

    for (int kt = 0; kt < 16; kt++) {
        const float* Bc = Bs + (kt & 1) * (64 * QP);
        const float* Vc = Vs + (kt & 1) * (64 * VP);
        if (kt < 15) {
            stage_tile(Bs + ((kt + 1) & 1) * (64 * QP),
                       Vs + ((kt + 1) & 1) * (64 * VP),
                       Kg, Vg, (kt + 1) * 64, tid);
            asm volatile("cp.async.commit_group;\n");
            asm volatile("cp.async.wait_group 1;\n");
        } else {
            asm volatile("cp.async.wait_group 0;\n");
        }
        __syncthreads();

        // ---- S = [Q|Q'] . [K|K']^T  (64x64, k=128) ----
        float accs[4][4];
        #pragma unroll
        for (int i = 0; i < 4; i++)
            #pragma unroll
            for (int q = 0; q < 4; q++) accs[i][q] = 0.0f;
        #pragma unroll
        for (int ks = 0; ks < 16; ks++) {
            int kk = ks * 8;
            unsigned a[4];
            a[0] = fbits(Qs[rb * QP + kk + c4]);
            a[1] = fbits(Qs[(rb + 8) * QP + kk + c4]);
            a[2] = fbits(Qs[rb * QP + kk + c4 + 4]);
            a[3] = fbits(Qs[(rb + 8) * QP + kk + c4 + 4]);
            #pragma unroll
            for (int ni = 0; ni < 4; ni++) {
                int col = wn * 32 + ni * 8 + g;
                unsigned b[2];
                b[0] = fbits(Bc[col * QP + kk + c4]);
                b[1] = fbits(Bc[col * QP + kk + c4 + 4]);
                mma8(accs[ni], a, b);
            }
        }

        // ---- P = exp(S); row sums ----
        #pragma unroll
        for (int hh = 0; hh < 2; hh++) {
            int r = rb + hh * 8;
            float part = 0.0f;
            #pragma unroll
            for (int ni = 0; ni < 4; ni++) {
                float p0 = __expf(accs[ni][hh * 2 + 0]);
                float p1 = __expf(accs[ni][hh * 2 + 1]);
                part += p0 + p1;
                int col = wn * 32 + ni * 8 + c4 * 2;
                *(float2*)(Ps + r * VP + col) = make_float2(p0, p1);
            }
            part += __shfl_xor_sync(0xffffffffu, part, 1);
            part += __shfl_xor_sync(0xffffffffu, part, 2);
            if (c4 == 0) atomicAdd(&lrow[r], part);
        }
        __syncthreads();

        // ---- O += P @ V (split-tf32 P) ----
        #pragma unroll
        for (int ks = 0; ks < 8; ks++) {
            int kk = ks * 8;
            float p0 = Ps[rb * VP + kk + c4];
            float p1 = Ps[(rb + 8) * VP + kk + c4];
            float p2 = Ps[rb * VP + kk + c4 + 4];
            float p3 = Ps[(rb + 8) * VP + kk + c4 + 4];
            unsigned ah[4] = { tf32b(p0), tf32b(p1), tf32b(p2), tf32b(p3) };
            unsigned al[4] = { tf32b(p0 - __uint_as_float(ah[0])),
                               tf32b(p1 - __uint_as_float(ah[1])),
                               tf32b(p2 - __uint_as_float(ah[2])),
                               tf32b(p3 - __uint_as_float(ah[3])) };
            #pragma unroll
            for (int ni = 0; ni < 4; ni++) {
                int col = wn * 32 + ni * 8 + g;
                unsigned b[2];
                b[0] = fbits(Vc[col * VP + kk + c4]);
                b[1] = fbits(Vc[col * VP + kk + c4 + 4]);
                mma8(acco[ni], ah, b);
                mma8(acco[ni], al, b);
            }
        }
        __syncthreads();
    }

    // ---- epilogue: O / l, fused transpose ----
    int batch = bh >> 3, h = bh & 7;
    #pragma unroll
    for (int hh = 0; hh < 2; hh++) {
        int r = rb + hh * 8;
        float inv = 1.0f / lrow[r];
        int l = q0 + r;
        #pragma unroll
        for (int ni = 0; ni < 4; ni++) {
            int d = wn * 32 + ni * 8 + c4 * 2;
            *(float2*)(out + ((size_t)(batch * Ln + l)) * Dn + h * DH + d) =
                make_float2(acco[ni][hh * 2] * inv, acco[ni][hh * 2 + 1] * inv);
        }
    }
}

// ---------------- launch ------------------------------------------------------
extern "C" void kernel_launch(void* const* d_in, const int* in_sizes, int n_in,
                              void* d_out, int out_size) {
    (void)in_sizes; (void)n_in; (void)out_size;
    const float* x    = (const float*)d_in[0];
    const float* W    = (const float*)d_in[1];
    const float* bias = (const float*)d_in[2];
    float* out = (float*)d_out;

    cudaFuncSetAttribute(attn_kernel,
                         cudaFuncAttributeMaxDynamicSharedMemorySize, ATT_SMEM);

    kp_kernel<<<Ln, 32>>>();

    dim3 pg(12, 32);
    proj_kernel<<<pg, 256>>>(x, W, bias);

    dim3 ag(16, BHn);
    attn_kernel<<<ag, 256, ATT_SMEM>>>(out);
}

// round 6
// speedup vs baseline: 3.2779x; 1.1036x over previous
#include <cuda_runtime.h>
#include <math.h>

#define Bn 4
#define Ln 1024
#define Dn 512
#define Hn 8
#define DH 64
#define BHn 32

// ---------------- scratch ----------------------------------------------------
__device__ float g_q[BHn * Ln * DH];      // full fp32 (Q' build needs precision)
__device__ float g_k[BHn * Ln * DH];      // tf32-pre-rounded
__device__ float g_vt[BHn * DH * Ln];     // V transposed [bh][d][kv], tf32-pre-rounded
__device__ float g_kp[Ln * DH];           // K' [k][0:32]=cos(kw),[32:64]=sin(kw), tf32

// ---------------- helpers ----------------------------------------------------
__device__ __forceinline__ unsigned tf32b(float x) {
    unsigned y;
    asm("cvt.rna.tf32.f32 %0, %1;" : "=r"(y) : "f"(x));
    return y;
}
__device__ __forceinline__ float tf32r(float x) { return __uint_as_float(tf32b(x)); }
__device__ __forceinline__ unsigned fbits(float x) { return __float_as_uint(x); }

__device__ __forceinline__ void mma8(float* c, const unsigned* a, const unsigned* b) {
    asm volatile(
        "mma.sync.aligned.m16n8k8.row.col.f32.tf32.tf32.f32 "
        "{%0,%1,%2,%3}, {%4,%5,%6,%7}, {%8,%9}, {%0,%1,%2,%3};\n"
        : "+f"(c[0]), "+f"(c[1]), "+f"(c[2]), "+f"(c[3])
        : "r"(a[0]), "r"(a[1]), "r"(a[2]), "r"(a[3]), "r"(b[0]), "r"(b[1]));
}

__device__ __forceinline__ void cpa16(unsigned dst, const float* src) {
    asm volatile("cp.async.cg.shared.global [%0], [%1], 16;\n" :: "r"(dst), "l"(src));
}
#define CP_COMMIT()  asm volatile("cp.async.commit_group;\n")
#define CP_WAIT(N)   asm volatile("cp.async.wait_group %0;\n" :: "n"(N))

// ---------------- kernel 1: K' table (tf32 pre-rounded) ----------------------
__global__ void kp_kernel() {
    int k = blockIdx.x;           // 0..1023
    int j = threadIdx.x;          // 0..31
    float w = expf(-(float)(2 * j) * 0.14391157f);
    float s, c;
    sincosf((float)k * w, &s, &c);
    g_kp[k * 64 + j]      = tf32r(c);
    g_kp[k * 64 + 32 + j] = tf32r(s);
}

// ---------------- kernel 2: proj GEMM (tf32 mma) -> Q,K,V^T scatter ----------
#define APAD 36
#define BPAD 136
__global__ __launch_bounds__(256) void proj_kernel(const float* __restrict__ x,
                                                   const float* __restrict__ W,
                                                   const float* __restrict__ bias) {
    __shared__ float As[128 * APAD];
    __shared__ float Bs[32 * BPAD];
    int bn = blockIdx.x;             // 0..11
    int bm = blockIdx.y;             // 0..31
    int m0 = bm * 128, n0 = bn * 128;
    int tid = threadIdx.x, lane = tid & 31, wid = tid >> 5;
    int wm = wid >> 1, wn = wid & 1;
    int g = lane >> 2, c4 = lane & 3;

    float acc[2][8][4];
    #pragma unroll
    for (int i = 0; i < 2; i++)
        #pragma unroll
        for (int j = 0; j < 8; j++)
            #pragma unroll
            for (int q = 0; q < 4; q++) acc[i][j][q] = 0.0f;

    for (int k0 = 0; k0 < 512; k0 += 32) {
        #pragma unroll
        for (int p = 0; p < 4; p++) {
            int r = (tid >> 3) + p * 32;
            int c = (tid & 7) * 4;
            float4 v = *(const float4*)(x + (size_t)(m0 + r) * 512 + k0 + c);
            float* a = As + r * APAD + c;
            a[0] = tf32r(v.x); a[1] = tf32r(v.y); a[2] = tf32r(v.z); a[3] = tf32r(v.w);
        }
        #pragma unroll
        for (int p = 0; p < 4; p++) {
            int r = (tid >> 5) + p * 8;
            int c = (tid & 31) * 4;
            float4 v = *(const float4*)(W + (size_t)(k0 + r) * 1536 + n0 + c);
            float* b = Bs + r * BPAD + c;
            b[0] = tf32r(v.x); b[1] = tf32r(v.y); b[2] = tf32r(v.z); b[3] = tf32r(v.w);
        }
        __syncthreads();
        #pragma unroll
        for (int ks = 0; ks < 4; ks++) {
            int kk = ks * 8;
            unsigned a[2][4];
            #pragma unroll
            for (int mi = 0; mi < 2; mi++) {
                int rb = wm * 32 + mi * 16 + g;
                a[mi][0] = fbits(As[rb * APAD + kk + c4]);
                a[mi][1] = fbits(As[(rb + 8) * APAD + kk + c4]);
                a[mi][2] = fbits(As[rb * APAD + kk + c4 + 4]);
                a[mi][3] = fbits(As[(rb + 8) * APAD + kk + c4 + 4]);
            }
            #pragma unroll
            for (int ni = 0; ni < 8; ni++) {
                int col = wn * 64 + ni * 8 + g;
                unsigned b[2];
                b[0] = fbits(Bs[(kk + c4) * BPAD + col]);
                b[1] = fbits(Bs[(kk + c4 + 4) * BPAD + col]);
                mma8(acc[0][ni], a[0], b);
                mma8(acc[1][ni], a[1], b);
            }
        }
        __syncthreads();
    }
    // epilogue: bias + scatter; K and V^T stored tf32-pre-rounded
    #pragma unroll
    for (int mi = 0; mi < 2; mi++) {
        #pragma unroll
        for (int hh = 0; hh < 2; hh++) {
            int r = wm * 32 + mi * 16 + g + hh * 8;
            int mglob = m0 + r;
            int batch = mglob >> 10, l = mglob & 1023;
            #pragma unroll
            for (int ni = 0; ni < 8; ni++) {
                int n = n0 + wn * 64 + ni * 8 + c4 * 2;
                float v0 = acc[mi][ni][hh * 2 + 0] + bias[n];
                float v1 = acc[mi][ni][hh * 2 + 1] + bias[n + 1];
                int h = n / 192;
                int rr = n - h * 192;
                int part = rr >> 6, d = rr & 63;
                size_t bh = (size_t)(batch * Hn + h);
                if (part == 0) {
                    *(float2*)(g_q + (bh * Ln + l) * DH + d) = make_float2(v0, v1);
                } else if (part == 1) {
                    *(float2*)(g_k + (bh * Ln + l) * DH + d) =
                        make_float2(tf32r(v0), tf32r(v1));
                } else {
                    g_vt[(bh * DH + d) * Ln + l]     = tf32r(v0);
                    g_vt[(bh * DH + d + 1) * Ln + l] = tf32r(v1);
                }
            }
        }
    }
}

// ---------------- kernel 3: fused attention, 2 blocks/SM ----------------------
// Smem: Qs[64][132] + Bs[64][132] + Vs[64][68] + Ps[64][68] + lrow[64]
//     = 102,912 B < 113,664 -> 2 blocks/SM.
// Single-buffered B and V; prefetch rotated so latency hides inside the iter:
//   V(kt) issued at iter top   (covered by S + exp),
//   B(kt+1) issued after sync_c (covered by PV).
#define QP 132
#define VP 68
#define SM_B  (64 * QP)
#define SM_V  (2 * 64 * QP)
#define SM_PS (2 * 64 * QP + 64 * VP)
#define SM_L  (SM_PS + 64 * VP)
#define ATT_SMEM ((SM_L + 64) * 4)

__device__ __forceinline__ void stage_B(float* Bdst, const float* Kg, int k0, int tid) {
    unsigned bB = (unsigned)__cvta_generic_to_shared(Bdst);
    #pragma unroll
    for (int p = 0; p < 8; p++) {
        int id = p * 256 + tid;       // 0..2047, 32 chunks/row
        int r = id >> 5;
        int c = id & 31;
        const float* src = (c < 16) ? (Kg + (size_t)(k0 + r) * 64 + c * 4)
                                    : (g_kp + (size_t)(k0 + r) * 64 + (c - 16) * 4);
        cpa16(bB + (unsigned)(r * QP + c * 4) * 4, src);
    }
}
__device__ __forceinline__ void stage_V(float* Vdst, const float* Vg, int k0, int tid) {
    unsigned bV = (unsigned)__cvta_generic_to_shared(Vdst);
    #pragma unroll
    for (int p = 0; p < 4; p++) {
        int id = p * 256 + tid;       // 0..1023, 16 chunks/row
        int r = id >> 4;
        int c = id & 15;
        cpa16(bV + (unsigned)(r * VP + c * 4) * 4, Vg + (size_t)r * Ln + k0 + c * 4);
    }
}

__global__ __launch_bounds__(256, 2) void attn_kernel(float* __restrict__ out) {
    extern __shared__ float sm[];
    float* Qs   = sm;            // [64][QP]  (Q | Q'), tf32, scaled 1/8
    float* Bs   = sm + SM_B;     // [64][QP]  (K | K')
    float* Vs   = sm + SM_V;     // [64][VP]  (V^T)
    float* Ps   = sm + SM_PS;    // [64][VP]
    float* lrow = sm + SM_L;     // [64]
    int qt = blockIdx.x, bh = blockIdx.y;
    int q0 = qt * 64;
    const float* Qg = g_q  + ((size_t)bh << 16);
    const float* Kg = g_k  + ((size_t)bh << 16);
    const float* Vg = g_vt + ((size_t)bh << 16);
    int tid = threadIdx.x, lane = tid & 31, wid = tid >> 5;
    int wm = wid >> 1, wn = wid & 1;     // 4 x 2 warps over 64x64
    int g = lane >> 2, c4 = lane & 3;

    // prologue: prefetch B(0) while building Q|Q'
    stage_B(Bs, Kg, 0, tid);
    CP_COMMIT();                         // group: B(0)

    {
        int r = tid >> 2;                 // 0..63
        int qq = (tid & 3) * 8;
        const float* src = Qg + (size_t)(q0 + r) * 64;
        float qa[8], qb[8];
        #pragma unroll
        for (int i = 0; i < 8; i += 4) {
            float4 v = *(const float4*)(src + qq + i);
            qa[i] = v.x; qa[i+1] = v.y; qa[i+2] = v.z; qa[i+3] = v.w;
            float4 u = *(const float4*)(src + 32 + qq + i);
            qb[i] = u.x; qb[i+1] = u.y; qb[i+2] = u.z; qb[i+3] = u.w;
        }
        float pos = (float)(q0 + r);
        float* qrow = Qs + r * QP;
        #pragma unroll
        for (int i = 0; i < 8; i++) {
            int j = qq + i;
            float w = expf(-(float)(2 * j) * 0.14391157f);
            float s, c;
            sincosf(pos * w, &s, &c);
            qrow[j]      = tf32r(0.125f * qa[i]);
            qrow[j + 32] = tf32r(0.125f * qb[i]);
            qrow[j + 64] = tf32r(0.125f * (qa[i] * s + qb[i] * c));
            qrow[j + 96] = tf32r(0.125f * (qb[i] * s - qa[i] * c));
        }
        if (tid < 64) lrow[tid] = 0.0f;
    }

    float acco[4][4];
    #pragma unroll
    for (int i = 0; i < 4; i++)
        #pragma unroll
        for (int q = 0; q < 4; q++) acco[i][q] = 0.0f;

    int rb = wm * 16 + g;

    for (int kt = 0; kt < 16; kt++) {
        // sync_a: retire PV(kt-1) reads of Vs/Ps (kt=0: Qs/lrow writes done)
        __syncthreads();
        stage_V(Vs, Vg, kt * 64, tid);
        CP_COMMIT();                     // group: V(kt). outstanding: {B(kt), V(kt)}
        CP_WAIT(1);                      // retire B(kt)
        __syncthreads();                 // sync_b: Bs (and Qs) visible to all

        // ---- S = [Q|Q'] . [K|K']^T  (64x64, k=128) ----
        float accs[4][4];
        #pragma unroll
        for (int i = 0; i < 4; i++)
            #pragma unroll
            for (int q = 0; q < 4; q++) accs[i][q] = 0.0f;
        #pragma unroll
        for (int ks = 0; ks < 16; ks++) {
            int kk = ks * 8;
            unsigned a[4];
            a[0] = fbits(Qs[rb * QP + kk + c4]);
            a[1] = fbits(Qs[(rb + 8) * QP + kk + c4]);
            a[2] = fbits(Qs[rb * QP + kk + c4 + 4]);
            a[3] = fbits(Qs[(rb + 8) * QP + kk + c4 + 4]);
            #pragma unroll
            for (int ni = 0; ni < 4; ni++) {
                int col = wn * 32 + ni * 8 + g;
                unsigned b[2];
                b[0] = fbits(Bs[col * QP + kk + c4]);
                b[1] = fbits(Bs[col * QP + kk + c4 + 4]);
                mma8(accs[ni], a, b);
            }
        }

        // ---- P = exp(S); row sums ----
        #pragma unroll
        for (int hh = 0; hh < 2; hh++) {
            int r = rb + hh * 8;
            float part = 0.0f;
            #pragma unroll
            for (int ni = 0; ni < 4; ni++) {
                float p0 = __expf(accs[ni][hh * 2 + 0]);
                float p1 = __expf(accs[ni][hh * 2 + 1]);
                part += p0 + p1;
                int col = wn * 32 + ni * 8 + c4 * 2;
                *(float2*)(Ps + r * VP + col) = make_float2(p0, p1);
            }
            part += __shfl_xor_sync(0xffffffffu, part, 1);
            part += __shfl_xor_sync(0xffffffffu, part, 2);
            if (c4 == 0) atomicAdd(&lrow[r], part);
        }

        CP_WAIT(0);                      // retire V(kt)
        __syncthreads();                 // sync_c: Vs + Ps visible; Bs reads retired
        if (kt < 15) {
            stage_B(Bs, Kg, (kt + 1) * 64, tid);
            CP_COMMIT();                 // group: B(kt+1), hidden under PV
        }

        // ---- O += P @ V (split-tf32 P) ----
        #pragma unroll
        for (int ks = 0; ks < 8; ks++) {
            int kk = ks * 8;
            float p0 = Ps[rb * VP + kk + c4];
            float p1 = Ps[(rb + 8) * VP + kk + c4];
            float p2 = Ps[rb * VP + kk + c4 + 4];
            float p3 = Ps[(rb + 8) * VP + kk + c4 + 4];
            unsigned ah[4] = { tf32b(p0), tf32b(p1), tf32b(p2), tf32b(p3) };
            unsigned al[4] = { tf32b(p0 - __uint_as_float(ah[0])),
                               tf32b(p1 - __uint_as_float(ah[1])),
                               tf32b(p2 - __uint_as_float(ah[2])),
                               tf32b(p3 - __uint_as_float(ah[3])) };
            #pragma unroll
            for (int ni = 0; ni < 4; ni++) {
                int col = wn * 32 + ni * 8 + g;
                unsigned b[2];
                b[0] = fbits(Vs[col * VP + kk + c4]);
                b[1] = fbits(Vs[col * VP + kk + c4 + 4]);
                mma8(acco[ni], ah, b);
                mma8(acco[ni], al, b);
            }
        }
    }

    // ---- epilogue: O / l, fused transpose ----
    int batch = bh >> 3, h = bh & 7;
    #pragma unroll
    for (int hh = 0; hh < 2; hh++) {
        int r = rb + hh * 8;
        float inv = 1.0f / lrow[r];
        int l = q0 + r;
        #pragma unroll
        for (int ni = 0; ni < 4; ni++) {
            int d = wn * 32 + ni * 8 + c4 * 2;
            *(float2*)(out + ((size_t)(batch * Ln + l)) * Dn + h * DH + d) =
                make_float2(acco[ni][hh * 2] * inv, acco[ni][hh * 2 + 1] * inv);
        }
    }
}

// ---------------- launch ------------------------------------------------------
extern "C" void kernel_launch(void* const* d_in, const int* in_sizes, int n_in,
                              void* d_out, int out_size) {
    (void)in_sizes; (void)n_in; (void)out_size;
    const float* x    = (const float*)d_in[0];
    const float* W    = (const float*)d_in[1];
    const float* bias = (const float*)d_in[2];
    float* out = (float*)d_out;

    cudaFuncSetAttribute(attn_kernel,
                         cudaFuncAttributeMaxDynamicSharedMemorySize, ATT_SMEM);

    kp_kernel<<<Ln, 32>>>();

    dim3 pg(12, 32);
    proj_kernel<<<pg, 256>>>(x, W, bias);

    dim3 ag(16, BHn);
    attn_kernel<<<ag, 256, ATT_SMEM>>>(out);
}

// round 7
// speedup vs baseline: 3.7512x; 1.1444x over previous
#include <cuda_runtime.h>
#include <math.h>

#define Bn 4
#define Ln 1024
#define Dn 512
#define Hn 8
#define DH 64
#define BHn 32

// ---------------- scratch ----------------------------------------------------
// Packed fragment layouts (tf32-pre-rounded), so attn staging is a linear copy
// and every mma operand is one LDS.128 / LDS.64.
// B-operand pack (K and K'):  [tile][ks][nfrag 8][lane 32][2]
//   element(ks,nf,lane=(g,c4),e) = OP[col = nf*8+g][k = ks*8+c4+4e]
// V-operand pack:             [tile][ks 8][dfrag 8][lane 32][2]
//   element = V^T[d = df*8+g][kv = ks*8+c4+4e]
__device__ float g_q[BHn * Ln * DH];        // fp32, row-major (Q' build needs it)
__device__ float g_kpack[BHn * 16 * 4096];  // K   : k-cols 0..63  (ks 0..7)
__device__ float g_kppack[16 * 4096];       // K'  : k-cols 64..127, bh-independent
__device__ float g_vpack[BHn * 16 * 4096];  // V^T

// ---------------- helpers ----------------------------------------------------
__device__ __forceinline__ unsigned tf32b(float x) {
    unsigned y;
    asm("cvt.rna.tf32.f32 %0, %1;" : "=r"(y) : "f"(x));
    return y;
}
__device__ __forceinline__ float tf32r(float x) { return __uint_as_float(tf32b(x)); }
__device__ __forceinline__ unsigned fbits(float x) { return __float_as_uint(x); }

__device__ __forceinline__ void mma8(float* c, const unsigned* a, const unsigned* b) {
    asm volatile(
        "mma.sync.aligned.m16n8k8.row.col.f32.tf32.tf32.f32 "
        "{%0,%1,%2,%3}, {%4,%5,%6,%7}, {%8,%9}, {%0,%1,%2,%3};\n"
        : "+f"(c[0]), "+f"(c[1]), "+f"(c[2]), "+f"(c[3])
        : "r"(a[0]), "r"(a[1]), "r"(a[2]), "r"(a[3]), "r"(b[0]), "r"(b[1]));
}

__device__ __forceinline__ void cpa16(unsigned dst, const float* src) {
    asm volatile("cp.async.cg.shared.global [%0], [%1], 16;\n" :: "r"(dst), "l"(src));
}
#define CP_COMMIT()  asm volatile("cp.async.commit_group;\n")
#define CP_WAIT(N)   asm volatile("cp.async.wait_group %0;\n" :: "n"(N))

// ---------------- kernel 1: K' table, packed ---------------------------------
__global__ void kp_kernel() {
    int kv = blockIdx.x;          // 0..1023
    int j  = threadIdx.x;         // 0..63 (K' column)
    int jj = (j < 32) ? j : (j - 32);
    float w = expf(-(float)(2 * jj) * 0.14391157f);
    float s, c;
    sincosf((float)kv * w, &s, &c);
    float val = (j < 32) ? c : s;
    int t = kv >> 6, nf = (kv >> 3) & 7, g = kv & 7;
    int ks = j >> 3, c4 = j & 3, e = (j >> 2) & 1;
    g_kppack[t * 4096 + ((ks * 8 + nf) * 32 + g * 4 + c4) * 2 + e] = tf32r(val);
}

// ---------------- kernel 2: proj GEMM -> Q, packed K, packed V^T --------------
#define APAD 36
#define BPAD 136
__global__ __launch_bounds__(256) void proj_kernel(const float* __restrict__ x,
                                                   const float* __restrict__ W,
                                                   const float* __restrict__ bias) {
    __shared__ float As[128 * APAD];
    __shared__ float Bs[32 * BPAD];
    int bn = blockIdx.x;             // 0..11
    int bm = blockIdx.y;             // 0..31
    int m0 = bm * 128, n0 = bn * 128;
    int tid = threadIdx.x, lane = tid & 31, wid = tid >> 5;
    int wm = wid >> 1, wn = wid & 1;
    int g = lane >> 2, c4 = lane & 3;

    float acc[2][8][4];
    #pragma unroll
    for (int i = 0; i < 2; i++)
        #pragma unroll
        for (int j = 0; j < 8; j++)
            #pragma unroll
            for (int q = 0; q < 4; q++) acc[i][j][q] = 0.0f;

    for (int k0 = 0; k0 < 512; k0 += 32) {
        #pragma unroll
        for (int p = 0; p < 4; p++) {
            int r = (tid >> 3) + p * 32;
            int c = (tid & 7) * 4;
            float4 v = *(const float4*)(x + (size_t)(m0 + r) * 512 + k0 + c);
            float* a = As + r * APAD + c;
            a[0] = tf32r(v.x); a[1] = tf32r(v.y); a[2] = tf32r(v.z); a[3] = tf32r(v.w);
        }
        #pragma unroll
        for (int p = 0; p < 4; p++) {
            int r = (tid >> 5) + p * 8;
            int c = (tid & 31) * 4;
            float4 v = *(const float4*)(W + (size_t)(k0 + r) * 1536 + n0 + c);
            float* b = Bs + r * BPAD + c;
            b[0] = tf32r(v.x); b[1] = tf32r(v.y); b[2] = tf32r(v.z); b[3] = tf32r(v.w);
        }
        __syncthreads();
        #pragma unroll
        for (int ks = 0; ks < 4; ks++) {
            int kk = ks * 8;
            unsigned a[2][4];
            #pragma unroll
            for (int mi = 0; mi < 2; mi++) {
                int rb = wm * 32 + mi * 16 + g;
                a[mi][0] = fbits(As[rb * APAD + kk + c4]);
                a[mi][1] = fbits(As[(rb + 8) * APAD + kk + c4]);
                a[mi][2] = fbits(As[rb * APAD + kk + c4 + 4]);
                a[mi][3] = fbits(As[(rb + 8) * APAD + kk + c4 + 4]);
            }
            #pragma unroll
            for (int ni = 0; ni < 8; ni++) {
                int col = wn * 64 + ni * 8 + g;
                unsigned b[2];
                b[0] = fbits(Bs[(kk + c4) * BPAD + col]);
                b[1] = fbits(Bs[(kk + c4 + 4) * BPAD + col]);
                mma8(acc[0][ni], a[0], b);
                mma8(acc[1][ni], a[1], b);
            }
        }
        __syncthreads();
    }
    // epilogue: bias + scatter. Q row-major fp32; K/V into packed tf32 layouts.
    #pragma unroll
    for (int mi = 0; mi < 2; mi++) {
        #pragma unroll
        for (int hh = 0; hh < 2; hh++) {
            int r = wm * 32 + mi * 16 + g + hh * 8;
            int mglob = m0 + r;
            int batch = mglob >> 10, l = mglob & 1023;
            int t = l >> 6;
            #pragma unroll
            for (int ni = 0; ni < 8; ni++) {
                int n = n0 + wn * 64 + ni * 8 + c4 * 2;
                float v0 = acc[mi][ni][hh * 2 + 0] + bias[n];
                float v1 = acc[mi][ni][hh * 2 + 1] + bias[n + 1];
                int h = n / 192;
                int rr = n - h * 192;
                int part = rr >> 6, d = rr & 63;
                size_t bh = (size_t)(batch * Hn + h);
                if (part == 0) {
                    *(float2*)(g_q + (bh * Ln + l) * DH + d) = make_float2(v0, v1);
                } else if (part == 1) {
                    // K pack: col = kv = l, k = d
                    int nf = (l >> 3) & 7, gg = l & 7;
                    size_t base = (bh * 16 + t) * 4096;
                    int ks0 = d >> 3;
                    g_kpack[base + ((ks0 * 8 + nf) * 32 + gg * 4 + (d & 3)) * 2 +
                            ((d >> 2) & 1)] = tf32r(v0);
                    int d1 = d + 1;
                    g_kpack[base + (((d1 >> 3) * 8 + nf) * 32 + gg * 4 + (d1 & 3)) * 2 +
                            ((d1 >> 2) & 1)] = tf32r(v1);
                } else {
                    // V pack: d-col = d, k = kv = l
                    int kv6 = l & 63;
                    int ks = kv6 >> 3, c4v = kv6 & 3, ev = (kv6 >> 2) & 1;
                    size_t base = (bh * 16 + t) * 4096;
                    g_vpack[base + ((ks * 8 + (d >> 3)) * 32 + (d & 7) * 4 + c4v) * 2 + ev] =
                        tf32r(v0);
                    int dd = d + 1;
                    g_vpack[base + ((ks * 8 + (dd >> 3)) * 32 + (dd & 7) * 4 + c4v) * 2 + ev] =
                        tf32r(v1);
                }
            }
        }
    }
}

// ---------------- kernel 3: fused attention, 128-q tiles, packed frags -------
// Smem (floats): Qs 16384 | Bs 8192 | Vs 4096 | Ps 128*68 | lrow 128 = 150016 B
#define PSP 68
#define SMF_BS 16384
#define SMF_VS 24576
#define SMF_PS 28672
#define SMF_L  (28672 + 128 * PSP)
#define ATT_SMEM ((SMF_L + 128) * 4)

__device__ __forceinline__ void stage_B(float* smem, int bh, int t, int tid) {
    unsigned dst = (unsigned)__cvta_generic_to_shared(smem + SMF_BS);
    const float* sk = g_kpack + ((size_t)bh * 16 + t) * 4096;
    const float* sp = g_kppack + (size_t)t * 4096;
    #pragma unroll
    for (int p = 0; p < 4; p++) {
        int idx = p * 256 + tid;                 // 0..1023 chunks of 16B
        cpa16(dst + idx * 16, sk + idx * 4);
        cpa16(dst + 16384 + idx * 16, sp + idx * 4);
    }
}
__device__ __forceinline__ void stage_V(float* smem, int bh, int t, int tid) {
    unsigned dst = (unsigned)__cvta_generic_to_shared(smem + SMF_VS);
    const float* sv = g_vpack + ((size_t)bh * 16 + t) * 4096;
    #pragma unroll
    for (int p = 0; p < 4; p++) {
        int idx = p * 256 + tid;
        cpa16(dst + idx * 16, sv + idx * 4);
    }
}

__global__ __launch_bounds__(256, 1) void attn_kernel(float* __restrict__ out) {
    extern __shared__ float sm[];
    float* Qs   = sm;              // packed A: [rf 8][ks 16][lane 32][4]
    float* Bs   = sm + SMF_BS;     // packed B: [ks 16][nf 8][lane 32][2]
    float* Vs   = sm + SMF_VS;     // packed B: [ks 8][df 8][lane 32][2]
    float* Ps   = sm + SMF_PS;     // [128][PSP]
    float* lrow = sm + SMF_L;      // [128]
    int qt = blockIdx.x, bh = blockIdx.y;
    int q0 = qt * 128;
    const float* Qg = g_q + ((size_t)bh << 16);
    int tid = threadIdx.x, lane = tid & 31, wid = tid >> 5;
    int wm = wid >> 1, wn = wid & 1;      // 4 x 2 warps, 32x32 tiles over 128x64
    int g = lane >> 2, c4 = lane & 3;

    stage_B(sm, bh, 0, tid);
    CP_COMMIT();                           // group: B(0)

    // ---- build Q | Q' (scaled 1/8, tf32) into packed A layout ----
    {
        int r = tid >> 1;                  // 0..127
        int half = tid & 1;                // 16 j's each
        const float* src = Qg + (size_t)(q0 + r) * 64 + half * 16;
        float qa[16], qb[16];
        #pragma unroll
        for (int i = 0; i < 16; i += 4) {
            float4 v = *(const float4*)(src + i);
            qa[i] = v.x; qa[i+1] = v.y; qa[i+2] = v.z; qa[i+3] = v.w;
            float4 u = *(const float4*)(src + 32 + i);
            qb[i] = u.x; qb[i+1] = u.y; qb[i+2] = u.z; qb[i+3] = u.w;
        }
        float pos = (float)(q0 + r);
        int gg = r & 7, hi = (r >> 3) & 1, rf = r >> 4;
        #pragma unroll
        for (int i = 0; i < 16; i++) {
            int j = half * 16 + i;
            float w = expf(-(float)(2 * j) * 0.14391157f);
            float s, c;
            sincosf(pos * w, &s, &c);
            float vals[4] = { 0.125f * qa[i], 0.125f * qb[i],
                              0.125f * (qa[i] * s + qb[i] * c),
                              0.125f * (qb[i] * s - qa[i] * c) };
            #pragma unroll
            for (int q = 0; q < 4; q++) {
                int cc = j + q * 32;
                int ks = cc >> 3;
                int ln = gg * 4 + (cc & 3);
                int el = ((cc >> 2) & 1) * 2 + hi;
                Qs[((rf * 16 + ks) * 32 + ln) * 4 + el] = tf32r(vals[q]);
            }
        }
        if (tid < 128) lrow[tid] = 0.0f;
    }

    float acco[2][4][4];
    #pragma unroll
    for (int mi = 0; mi < 2; mi++)
        #pragma unroll
        for (int j = 0; j < 4; j++)
            #pragma unroll
            for (int q = 0; q < 4; q++) acco[mi][j][q] = 0.0f;

    for (int kt = 0; kt < 16; kt++) {
        __syncthreads();                   // A: PV(kt-1) done with Vs/Ps
        stage_V(sm, bh, kt, tid);
        CP_COMMIT();                       // outstanding: {B(kt), V(kt)}
        CP_WAIT(1);                        // B(kt) arrived
        __syncthreads();                   // B: Bs (and Qs at kt=0) visible

        // ---- S = [Q|Q'] . [K|K']^T  (32x32 per warp, k=128) ----
        float accs[2][4][4];
        #pragma unroll
        for (int mi = 0; mi < 2; mi++)
            #pragma unroll
            for (int j = 0; j < 4; j++)
                #pragma unroll
                for (int q = 0; q < 4; q++) accs[mi][j][q] = 0.0f;
        #pragma unroll
        for (int ks = 0; ks < 16; ks++) {
            unsigned a[2][4];
            #pragma unroll
            for (int mi = 0; mi < 2; mi++) {
                float4 av = *(const float4*)(Qs + (((wm * 2 + mi) * 16 + ks) * 32 + lane) * 4);
                a[mi][0] = fbits(av.x); a[mi][1] = fbits(av.y);
                a[mi][2] = fbits(av.z); a[mi][3] = fbits(av.w);
            }
            #pragma unroll
            for (int ni = 0; ni < 4; ni++) {
                float2 bv = *(const float2*)(Bs + ((ks * 8 + wn * 4 + ni) * 32 + lane) * 2);
                unsigned b[2] = { fbits(bv.x), fbits(bv.y) };
                mma8(accs[0][ni], a[0], b);
                mma8(accs[1][ni], a[1], b);
            }
        }

        // ---- P = exp(S); Ps stores; row sums ----
        #pragma unroll
        for (int mi = 0; mi < 2; mi++)
            #pragma unroll
            for (int hh = 0; hh < 2; hh++) {
                int r = wm * 32 + mi * 16 + g + hh * 8;
                float part = 0.0f;
                #pragma unroll
                for (int ni = 0; ni < 4; ni++) {
                    float p0 = __expf(accs[mi][ni][hh * 2 + 0]);
                    float p1 = __expf(accs[mi][ni][hh * 2 + 1]);
                    part += p0 + p1;
                    *(float2*)(Ps + r * PSP + wn * 32 + ni * 8 + c4 * 2) =
                        make_float2(p0, p1);
                }
                part += __shfl_xor_sync(0xffffffffu, part, 1);
                part += __shfl_xor_sync(0xffffffffu, part, 2);
                if (c4 == 0) atomicAdd(&lrow[r], part);
            }

        CP_WAIT(0);                        // V(kt) arrived
        __syncthreads();                   // C: Vs+Ps visible; Bs reads retired
        if (kt < 15) {
            stage_B(sm, bh, kt + 1, tid);
            CP_COMMIT();                   // hidden under PV
        }

        // ---- O += P @ V  (split-tf32 P, 32x32 per warp, k=64) ----
        #pragma unroll
        for (int ks = 0; ks < 8; ks++) {
            int kk = ks * 8;
            unsigned ah[2][4], al[2][4];
            #pragma unroll
            for (int mi = 0; mi < 2; mi++) {
                int r = wm * 32 + mi * 16 + g;
                float p0 = Ps[r * PSP + kk + c4];
                float p1 = Ps[(r + 8) * PSP + kk + c4];
                float p2 = Ps[r * PSP + kk + c4 + 4];
                float p3 = Ps[(r + 8) * PSP + kk + c4 + 4];
                ah[mi][0] = tf32b(p0); ah[mi][1] = tf32b(p1);
                ah[mi][2] = tf32b(p2); ah[mi][3] = tf32b(p3);
                al[mi][0] = tf32b(p0 - __uint_as_float(ah[mi][0]));
                al[mi][1] = tf32b(p1 - __uint_as_float(ah[mi][1]));
                al[mi][2] = tf32b(p2 - __uint_as_float(ah[mi][2]));
                al[mi][3] = tf32b(p3 - __uint_as_float(ah[mi][3]));
            }
            #pragma unroll
            for (int ni = 0; ni < 4; ni++) {
                float2 bv = *(const float2*)(Vs + ((ks * 8 + wn * 4 + ni) * 32 + lane) * 2);
                unsigned b[2] = { fbits(bv.x), fbits(bv.y) };
                mma8(acco[0][ni], ah[0], b);
                mma8(acco[0][ni], al[0], b);
                mma8(acco[1][ni], ah[1], b);
                mma8(acco[1][ni], al[1], b);
            }
        }
    }

    // ---- epilogue: O / l, fused transpose to [B, L, D] ----
    int batch = bh >> 3, h = bh & 7;
    #pragma unroll
    for (int mi = 0; mi < 2; mi++)
        #pragma unroll
        for (int hh = 0; hh < 2; hh++) {
            int r = wm * 32 + mi * 16 + g + hh * 8;
            float inv = 1.0f / lrow[r];
            int l = q0 + r;
            #pragma unroll
            for (int ni = 0; ni < 4; ni++) {
                int d = wn * 32 + ni * 8 + c4 * 2;
                *(float2*)(out + ((size_t)(batch * Ln + l)) * Dn + h * DH + d) =
                    make_float2(acco[mi][ni][hh * 2] * inv,
                                acco[mi][ni][hh * 2 + 1] * inv);
            }
        }
}

// ---------------- launch ------------------------------------------------------
extern "C" void kernel_launch(void* const* d_in, const int* in_sizes, int n_in,
                              void* d_out, int out_size) {
    (void)in_sizes; (void)n_in; (void)out_size;
    const float* x    = (const float*)d_in[0];
    const float* W    = (const float*)d_in[1];
    const float* bias = (const float*)d_in[2];
    float* out = (float*)d_out;

    cudaFuncSetAttribute(attn_kernel,
                         cudaFuncAttributeMaxDynamicSharedMemorySize, ATT_SMEM);

    kp_kernel<<<Ln, 64>>>();

    dim3 pg(12, 32);
    proj_kernel<<<pg, 256>>>(x, W, bias);

    dim3 ag(8, BHn);
    attn_kernel<<<ag, 256, ATT_SMEM>>>(out);
}

// round 9
// speedup vs baseline: 4.1285x; 1.1006x over previous
#include <cuda_runtime.h>
#include <math.h>

#define Bn 4
#define Ln 1024
#define Dn 512
#define Hn 8
#define DH 64
#define BHn 32

// ---------------- scratch ----------------------------------------------------
// Packed fragment layouts (tf32-pre-rounded): attn staging is a linear copy,
// every mma operand is one LDS.128 / LDS.64.
__device__ float g_q[BHn * Ln * DH];        // fp32, row-major (Q' build needs it)
__device__ float g_kpack[BHn * 16 * 4096];  // K   packed
__device__ float g_kppack[16 * 4096];       // K'  packed (bh-independent)
__device__ float g_vpack[BHn * 16 * 4096];  // V^T packed

// ---------------- helpers ----------------------------------------------------
__device__ __forceinline__ unsigned tf32b(float x) {
    unsigned y;
    asm("cvt.rna.tf32.f32 %0, %1;" : "=r"(y) : "f"(x));
    return y;
}
__device__ __forceinline__ float tf32r(float x) { return __uint_as_float(tf32b(x)); }
__device__ __forceinline__ unsigned fbits(float x) { return __float_as_uint(x); }

__device__ __forceinline__ void mma8(float* c, const unsigned* a, const unsigned* b) {
    asm volatile(
        "mma.sync.aligned.m16n8k8.row.col.f32.tf32.tf32.f32 "
        "{%0,%1,%2,%3}, {%4,%5,%6,%7}, {%8,%9}, {%0,%1,%2,%3};\n"
        : "+f"(c[0]), "+f"(c[1]), "+f"(c[2]), "+f"(c[3])
        : "r"(a[0]), "r"(a[1]), "r"(a[2]), "r"(a[3]), "r"(b[0]), "r"(b[1]));
}

__device__ __forceinline__ void cpa16(unsigned dst, const float* src) {
    asm volatile("cp.async.cg.shared.global [%0], [%1], 16;\n" :: "r"(dst), "l"(src));
}
#define CP_COMMIT()  asm volatile("cp.async.commit_group;\n")
#define CP_WAIT(N)   asm volatile("cp.async.wait_group %0;\n" :: "n"(N))

// ---------------- kernel 1: K' table, packed ---------------------------------
__global__ void kp_kernel() {
    int kv = blockIdx.x;          // 0..1023
    int j  = threadIdx.x;         // 0..63 (K' column)
    int jj = (j < 32) ? j : (j - 32);
    float w = expf(-(float)(2 * jj) * 0.14391157f);
    float s, c;
    sincosf((float)kv * w, &s, &c);
    float val = (j < 32) ? c : s;
    int t = kv >> 6, nf = (kv >> 3) & 7, g = kv & 7;
    int ks = j >> 3, c4 = j & 3, e = (j >> 2) & 1;
    g_kppack[t * 4096 + ((ks * 8 + nf) * 32 + g * 4 + c4) * 2 + e] = tf32r(val);
}

// ---------------- kernel 2: proj GEMM -> Q, packed K, packed V^T --------------
#define APAD 36
#define BPAD 136
__global__ __launch_bounds__(256) void proj_kernel(const float* __restrict__ x,
                                                   const float* __restrict__ W,
                                                   const float* __restrict__ bias) {
    __shared__ float As[128 * APAD];
    __shared__ float Bs[32 * BPAD];
    int bn = blockIdx.x;             // 0..11
    int bm = blockIdx.y;             // 0..31
    int m0 = bm * 128, n0 = bn * 128;
    int tid = threadIdx.x, lane = tid & 31, wid = tid >> 5;
    int wm = wid >> 1, wn = wid & 1;
    int g = lane >> 2, c4 = lane & 3;

    float acc[2][8][4];
    #pragma unroll
    for (int i = 0; i < 2; i++)
        #pragma unroll
        for (int j = 0; j < 8; j++)
            #pragma unroll
            for (int q = 0; q < 4; q++) acc[i][j][q] = 0.0f;

    for (int k0 = 0; k0 < 512; k0 += 32) {
        #pragma unroll
        for (int p = 0; p < 4; p++) {
            int r = (tid >> 3) + p * 32;
            int c = (tid & 7) * 4;
            float4 v = *(const float4*)(x + (size_t)(m0 + r) * 512 + k0 + c);
            float* a = As + r * APAD + c;
            a[0] = tf32r(v.x); a[1] = tf32r(v.y); a[2] = tf32r(v.z); a[3] = tf32r(v.w);
        }
        #pragma unroll
        for (int p = 0; p < 4; p++) {
            int r = (tid >> 5) + p * 8;
            int c = (tid & 31) * 4;
            float4 v = *(const float4*)(W + (size_t)(k0 + r) * 1536 + n0 + c);
            float* b = Bs + r * BPAD + c;
            b[0] = tf32r(v.x); b[1] = tf32r(v.y); b[2] = tf32r(v.z); b[3] = tf32r(v.w);
        }
        __syncthreads();
        #pragma unroll
        for (int ks = 0; ks < 4; ks++) {
            int kk = ks * 8;
            unsigned a[2][4];
            #pragma unroll
            for (int mi = 0; mi < 2; mi++) {
                int rb = wm * 32 + mi * 16 + g;
                a[mi][0] = fbits(As[rb * APAD + kk + c4]);
                a[mi][1] = fbits(As[(rb + 8) * APAD + kk + c4]);
                a[mi][2] = fbits(As[rb * APAD + kk + c4 + 4]);
                a[mi][3] = fbits(As[(rb + 8) * APAD + kk + c4 + 4]);
            }
            #pragma unroll
            for (int ni = 0; ni < 8; ni++) {
                int col = wn * 64 + ni * 8 + g;
                unsigned b[2];
                b[0] = fbits(Bs[(kk + c4) * BPAD + col]);
                b[1] = fbits(Bs[(kk + c4 + 4) * BPAD + col]);
                mma8(acc[0][ni], a[0], b);
                mma8(acc[1][ni], a[1], b);
            }
        }
        __syncthreads();
    }
    // epilogue: bias + scatter. Q row-major fp32; K/V into packed tf32 layouts.
    #pragma unroll
    for (int mi = 0; mi < 2; mi++) {
        #pragma unroll
        for (int hh = 0; hh < 2; hh++) {
            int r = wm * 32 + mi * 16 + g + hh * 8;
            int mglob = m0 + r;
            int batch = mglob >> 10, l = mglob & 1023;
            int t = l >> 6;
            #pragma unroll
            for (int ni = 0; ni < 8; ni++) {
                int n = n0 + wn * 64 + ni * 8 + c4 * 2;
                float v0 = acc[mi][ni][hh * 2 + 0] + bias[n];
                float v1 = acc[mi][ni][hh * 2 + 1] + bias[n + 1];
                int h = n / 192;
                int rr = n - h * 192;
                int part = rr >> 6, d = rr & 63;
                size_t bh = (size_t)(batch * Hn + h);
                if (part == 0) {
                    *(float2*)(g_q + (bh * Ln + l) * DH + d) = make_float2(v0, v1);
                } else if (part == 1) {
                    int nf = (l >> 3) & 7, gg = l & 7;
                    size_t base = (bh * 16 + t) * 4096;
                    int ks0 = d >> 3;
                    g_kpack[base + ((ks0 * 8 + nf) * 32 + gg * 4 + (d & 3)) * 2 +
                            ((d >> 2) & 1)] = tf32r(v0);
                    int d1 = d + 1;
                    g_kpack[base + (((d1 >> 3) * 8 + nf) * 32 + gg * 4 + (d1 & 3)) * 2 +
                            ((d1 >> 2) & 1)] = tf32r(v1);
                } else {
                    int kv6 = l & 63;
                    int ks = kv6 >> 3, c4v = kv6 & 3, ev = (kv6 >> 2) & 1;
                    size_t base = (bh * 16 + t) * 4096;
                    g_vpack[base + ((ks * 8 + (d >> 3)) * 32 + (d & 7) * 4 + c4v) * 2 + ev] =
                        tf32r(v0);
                    int dd = d + 1;
                    g_vpack[base + ((ks * 8 + (dd >> 3)) * 32 + (dd & 7) * 4 + c4v) * 2 + ev] =
                        tf32r(v1);
                }
            }
        }
    }
}

// ---------------- kernel 3: fused attention (single-tf32 PV) ------------------
#define PSP 68
#define SMF_BS 16384
#define SMF_VS 24576
#define SMF_PS 28672
#define SMF_L  (28672 + 128 * PSP)
#define ATT_SMEM ((SMF_L + 128) * 4)

__device__ __forceinline__ void stage_B(float* smem, int bh, int t, int tid) {
    unsigned dst = (unsigned)__cvta_generic_to_shared(smem + SMF_BS);
    const float* sk = g_kpack + ((size_t)bh * 16 + t) * 4096;
    const float* sp = g_kppack + (size_t)t * 4096;
    #pragma unroll
    for (int p = 0; p < 4; p++) {
        int idx = p * 256 + tid;
        cpa16(dst + idx * 16, sk + idx * 4);
        cpa16(dst + 16384 + idx * 16, sp + idx * 4);
    }
}
__device__ __forceinline__ void stage_V(float* smem, int bh, int t, int tid) {
    unsigned dst = (unsigned)__cvta_generic_to_shared(smem + SMF_VS);
    const float* sv = g_vpack + ((size_t)bh * 16 + t) * 4096;
    #pragma unroll
    for (int p = 0; p < 4; p++) {
        int idx = p * 256 + tid;
        cpa16(dst + idx * 16, sv + idx * 4);
    }
}

__global__ __launch_bounds__(256, 1) void attn_kernel(float* __restrict__ out) {
    extern __shared__ float sm[];
    float* Qs   = sm;              // packed A: [rf 8][ks 16][lane 32][4]
    float* Bs   = sm + SMF_BS;     // packed B: [ks 16][nf 8][lane 32][2]
    float* Vs   = sm + SMF_VS;     // packed B: [ks 8][df 8][lane 32][2]
    float* Ps   = sm + SMF_PS;     // [128][PSP]
    float* lrow = sm + SMF_L;      // [128]
    int qt = blockIdx.x, bh = blockIdx.y;
    int q0 = qt * 128;
    const float* Qg = g_q + ((size_t)bh << 16);
    int tid = threadIdx.x, lane = tid & 31, wid = tid >> 5;
    int wm = wid >> 1, wn = wid & 1;      // 4 x 2 warps, 32x32 tiles over 128x64
    int g = lane >> 2, c4 = lane & 3;

    stage_B(sm, bh, 0, tid);
    CP_COMMIT();                           // group: B(0)

    // ---- build Q | Q' (scaled 1/8, tf32) into packed A layout ----
    {
        int r = tid >> 1;                  // 0..127
        int half = tid & 1;                // 16 j's each
        const float* src = Qg + (size_t)(q0 + r) * 64 + half * 16;
        float qa[16], qb[16];
        #pragma unroll
        for (int i = 0; i < 16; i += 4) {
            float4 v = *(const float4*)(src + i);
            qa[i] = v.x; qa[i+1] = v.y; qa[i+2] = v.z; qa[i+3] = v.w;
            float4 u = *(const float4*)(src + 32 + i);
            qb[i] = u.x; qb[i+1] = u.y; qb[i+2] = u.z; qb[i+3] = u.w;
        }
        float pos = (float)(q0 + r);
        int gg = r & 7, hi = (r >> 3) & 1, rf = r >> 4;
        #pragma unroll
        for (int i = 0; i < 16; i++) {
            int j = half * 16 + i;
            float w = expf(-(float)(2 * j) * 0.14391157f);
            float s, c;
            sincosf(pos * w, &s, &c);
            float vals[4] = { 0.125f * qa[i], 0.125f * qb[i],
                              0.125f * (qa[i] * s + qb[i] * c),
                              0.125f * (qb[i] * s - qa[i] * c) };
            #pragma unroll
            for (int q = 0; q < 4; q++) {
                int cc = j + q * 32;
                int ks = cc >> 3;
                int ln = gg * 4 + (cc & 3);
                int el = ((cc >> 2) & 1) * 2 + hi;
                Qs[((rf * 16 + ks) * 32 + ln) * 4 + el] = tf32r(vals[q]);
            }
        }
        if (tid < 128) lrow[tid] = 0.0f;
    }

    float acco[2][4][4];
    #pragma unroll
    for (int mi = 0; mi < 2; mi++)
        #pragma unroll
        for (int j = 0; j < 4; j++)
            #pragma unroll
            for (int q = 0; q < 4; q++) acco[mi][j][q] = 0.0f;

    for (int kt = 0; kt < 16; kt++) {
        __syncthreads();                   // A: PV(kt-1) done with Vs/Ps
        stage_V(sm, bh, kt, tid);
        CP_COMMIT();                       // outstanding: {B(kt), V(kt)}
        CP_WAIT(1);                        // B(kt) arrived
        __syncthreads();                   // B: Bs (and Qs at kt=0) visible

        // ---- S = [Q|Q'] . [K|K']^T  (32x32 per warp, k=128) ----
        float accs[2][4][4];
        #pragma unroll
        for (int mi = 0; mi < 2; mi++)
            #pragma unroll
            for (int j = 0; j < 4; j++)
                #pragma unroll
                for (int q = 0; q < 4; q++) accs[mi][j][q] = 0.0f;
        #pragma unroll
        for (int ks = 0; ks < 16; ks++) {
            unsigned a[2][4];
            #pragma unroll
            for (int mi = 0; mi < 2; mi++) {
                float4 av = *(const float4*)(Qs + (((wm * 2 + mi) * 16 + ks) * 32 + lane) * 4);
                a[mi][0] = fbits(av.x); a[mi][1] = fbits(av.y);
                a[mi][2] = fbits(av.z); a[mi][3] = fbits(av.w);
            }
            #pragma unroll
            for (int ni = 0; ni < 4; ni++) {
                float2 bv = *(const float2*)(Bs + ((ks * 8 + wn * 4 + ni) * 32 + lane) * 2);
                unsigned b[2] = { fbits(bv.x), fbits(bv.y) };
                mma8(accs[0][ni], a[0], b);
                mma8(accs[1][ni], a[1], b);
            }
        }

        // ---- P = exp(S); Ps stores; row sums ----
        #pragma unroll
        for (int mi = 0; mi < 2; mi++)
            #pragma unroll
            for (int hh = 0; hh < 2; hh++) {
                int r = wm * 32 + mi * 16 + g + hh * 8;
                float part = 0.0f;
                #pragma unroll
                for (int ni = 0; ni < 4; ni++) {
                    float p0 = __expf(accs[mi][ni][hh * 2 + 0]);
                    float p1 = __expf(accs[mi][ni][hh * 2 + 1]);
                    part += p0 + p1;
                    *(float2*)(Ps + r * PSP + wn * 32 + ni * 8 + c4 * 2) =
                        make_float2(p0, p1);
                }
                part += __shfl_xor_sync(0xffffffffu, part, 1);
                part += __shfl_xor_sync(0xffffffffu, part, 2);
                if (c4 == 0) atomicAdd(&lrow[r], part);
            }

        CP_WAIT(0);                        // V(kt) arrived
        __syncthreads();                   // C: Vs+Ps visible; Bs reads retired
        if (kt < 15) {
            stage_B(sm, bh, kt + 1, tid);
            CP_COMMIT();                   // hidden under PV
        }

        // ---- O += P @ V  (single-tf32 P, 32x32 per warp, k=64) ----
        #pragma unroll
        for (int ks = 0; ks < 8; ks++) {
            int kk = ks * 8;
            unsigned ah[2][4];
            #pragma unroll
            for (int mi = 0; mi < 2; mi++) {
                int r = wm * 32 + mi * 16 + g;
                ah[mi][0] = tf32b(Ps[r * PSP + kk + c4]);
                ah[mi][1] = tf32b(Ps[(r + 8) * PSP + kk + c4]);
                ah[mi][2] = tf32b(Ps[r * PSP + kk + c4 + 4]);
                ah[mi][3] = tf32b(Ps[(r + 8) * PSP + kk + c4 + 4]);
            }
            #pragma unroll
            for (int ni = 0; ni < 4; ni++) {
                float2 bv = *(const float2*)(Vs + ((ks * 8 + wn * 4 + ni) * 32 + lane) * 2);
                unsigned b[2] = { fbits(bv.x), fbits(bv.y) };
                mma8(acco[0][ni], ah[0], b);
                mma8(acco[1][ni], ah[1], b);
            }
        }
    }

    // ---- epilogue: O / l, fused transpose to [B, L, D] ----
    int batch = bh >> 3, h = bh & 7;
    #pragma unroll
    for (int mi = 0; mi < 2; mi++)
        #pragma unroll
        for (int hh = 0; hh < 2; hh++) {
            int r = wm * 32 + mi * 16 + g + hh * 8;
            float inv = 1.0f / lrow[r];
            int l = q0 + r;
            #pragma unroll
            for (int ni = 0; ni < 4; ni++) {
                int d = wn * 32 + ni * 8 + c4 * 2;
                *(float2*)(out + ((size_t)(batch * Ln + l)) * Dn + h * DH + d) =
                    make_float2(acco[mi][ni][hh * 2] * inv,
                                acco[mi][ni][hh * 2 + 1] * inv);
            }
        }
}

// ---------------- launch ------------------------------------------------------
extern "C" void kernel_launch(void* const* d_in, const int* in_sizes, int n_in,
                              void* d_out, int out_size) {
    (void)in_sizes; (void)n_in; (void)out_size;
    const float* x    = (const float*)d_in[0];
    const float* W    = (const float*)d_in[1];
    const float* bias = (const float*)d_in[2];
    float* out = (float*)d_out;

    cudaFuncSetAttribute(attn_kernel,
                         cudaFuncAttributeMaxDynamicSharedMemorySize, ATT_SMEM);

    kp_kernel<<<Ln, 64>>>();

    dim3 pg(12, 32);
    proj_kernel<<<pg, 256>>>(x, W, bias);

    dim3 ag(8, BHn);
    attn_kernel<<<ag, 256, ATT_SMEM>>>(out);
}

// round 11
// speedup vs baseline: 5.8006x; 1.4050x over previous
#include <cuda_runtime.h>
#include <cuda_fp16.h>
#include <math.h>

#define Bn 4
#define Ln 1024
#define Dn 512
#define Hn 8
#define DH 64
#define BHn 32

// ---------------- scratch ----------------------------------------------------
// fp16 packed fragment layouts for m16n8k16:
//  B-pack (K, K', V^T): [ks][nf 8][lane 32][4 halfs]  -> one LDS.64 per frag
//  A-pack (Q|Q'):       [rf 8][ks 8][lane 32][8 halfs] -> one LDS.128 per frag
__device__ float  g_q[BHn * Ln * DH];         // fp32 (Q' build needs precision)
__device__ __half g_kpack[BHn * 16 * 4096];   // K   (ks 0..3 per tile)
__device__ __half g_kppack[16 * 4096];        // K'  (bh-independent)
__device__ __half g_vpack[BHn * 16 * 4096];   // V^T

// ---------------- helpers ----------------------------------------------------
__device__ __forceinline__ unsigned tf32b(float x) {
    unsigned y;
    asm("cvt.rna.tf32.f32 %0, %1;" : "=r"(y) : "f"(x));
    return y;
}
__device__ __forceinline__ float tf32r(float x) { return __uint_as_float(tf32b(x)); }
__device__ __forceinline__ unsigned fbits(float x) { return __float_as_uint(x); }

__device__ __forceinline__ void mma8(float* c, const unsigned* a, const unsigned* b) {
    asm volatile(
        "mma.sync.aligned.m16n8k8.row.col.f32.tf32.tf32.f32 "
        "{%0,%1,%2,%3}, {%4,%5,%6,%7}, {%8,%9}, {%0,%1,%2,%3};\n"
        : "+f"(c[0]), "+f"(c[1]), "+f"(c[2]), "+f"(c[3])
        : "r"(a[0]), "r"(a[1]), "r"(a[2]), "r"(a[3]), "r"(b[0]), "r"(b[1]));
}

__device__ __forceinline__ void mma16(float* c, const uint4 a, const uint2 b) {
    asm volatile(
        "mma.sync.aligned.m16n8k16.row.col.f32.f16.f16.f32 "
        "{%0,%1,%2,%3}, {%4,%5,%6,%7}, {%8,%9}, {%0,%1,%2,%3};\n"
        : "+f"(c[0]), "+f"(c[1]), "+f"(c[2]), "+f"(c[3])
        : "r"(a.x), "r"(a.y), "r"(a.z), "r"(a.w), "r"(b.x), "r"(b.y));
}

__device__ __forceinline__ unsigned h2u(float2 f) {
    __half2 h = __floats2half2_rn(f.x, f.y);
    return *reinterpret_cast<unsigned*>(&h);
}

__device__ __forceinline__ void cpa16(unsigned dst, const void* src) {
    asm volatile("cp.async.cg.shared.global [%0], [%1], 16;\n" :: "r"(dst), "l"(src));
}
#define CP_COMMIT()  asm volatile("cp.async.commit_group;\n")
#define CP_WAIT(N)   asm volatile("cp.async.wait_group %0;\n" :: "n"(N))

// ---------------- kernel 1: K' table (fp16, packed) ---------------------------
__global__ void kp_kernel() {
    int kv = blockIdx.x;          // 0..1023
    int j  = threadIdx.x;         // 0..63 (K' column = attn k 64+j)
    int jj = (j < 32) ? j : (j - 32);
    float w = expf(-(float)(2 * jj) * 0.14391157f);
    float s, c;
    sincosf((float)kv * w, &s, &c);
    float val = (j < 32) ? c : s;
    int t = kv >> 6, nf = (kv >> 3) & 7, g = kv & 7;
    int ks = j >> 4, kd = j & 15;
    int c4 = (kd & 7) >> 1, hx = kd & 1, br = kd >> 3;
    g_kppack[t * 4096 + ((ks * 8 + nf) * 32 + g * 4 + c4) * 4 + br * 2 + hx] =
        __float2half_rn(val);
}

// ---------------- kernel 2: proj GEMM (tf32) -> Q, fp16-packed K / V^T --------
#define APAD 36
#define BPAD 136
__global__ __launch_bounds__(256) void proj_kernel(const float* __restrict__ x,
                                                   const float* __restrict__ W,
                                                   const float* __restrict__ bias) {
    __shared__ float As[128 * APAD];
    __shared__ float Bsm[32 * BPAD];
    int bn = blockIdx.x;             // 0..11
    int bm = blockIdx.y;             // 0..31
    int m0 = bm * 128, n0 = bn * 128;
    int tid = threadIdx.x, lane = tid & 31, wid = tid >> 5;
    int wm = wid >> 1, wn = wid & 1;
    int g = lane >> 2, c4 = lane & 3;

    float acc[2][8][4];
    #pragma unroll
    for (int i = 0; i < 2; i++)
        #pragma unroll
        for (int j = 0; j < 8; j++)
            #pragma unroll
            for (int q = 0; q < 4; q++) acc[i][j][q] = 0.0f;

    for (int k0 = 0; k0 < 512; k0 += 32) {
        #pragma unroll
        for (int p = 0; p < 4; p++) {
            int r = (tid >> 3) + p * 32;
            int c = (tid & 7) * 4;
            float4 v = *(const float4*)(x + (size_t)(m0 + r) * 512 + k0 + c);
            float* a = As + r * APAD + c;
            a[0] = tf32r(v.x); a[1] = tf32r(v.y); a[2] = tf32r(v.z); a[3] = tf32r(v.w);
        }
        #pragma unroll
        for (int p = 0; p < 4; p++) {
            int r = (tid >> 5) + p * 8;
            int c = (tid & 31) * 4;
            float4 v = *(const float4*)(W + (size_t)(k0 + r) * 1536 + n0 + c);
            float* b = Bsm + r * BPAD + c;
            b[0] = tf32r(v.x); b[1] = tf32r(v.y); b[2] = tf32r(v.z); b[3] = tf32r(v.w);
        }
        __syncthreads();
        #pragma unroll
        for (int ks = 0; ks < 4; ks++) {
            int kk = ks * 8;
            unsigned a[2][4];
            #pragma unroll
            for (int mi = 0; mi < 2; mi++) {
                int rb = wm * 32 + mi * 16 + g;
                a[mi][0] = fbits(As[rb * APAD + kk + c4]);
                a[mi][1] = fbits(As[(rb + 8) * APAD + kk + c4]);
                a[mi][2] = fbits(As[rb * APAD + kk + c4 + 4]);
                a[mi][3] = fbits(As[(rb + 8) * APAD + kk + c4 + 4]);
            }
            #pragma unroll
            for (int ni = 0; ni < 8; ni++) {
                int col = wn * 64 + ni * 8 + g;
                unsigned b[2];
                b[0] = fbits(Bsm[(kk + c4) * BPAD + col]);
                b[1] = fbits(Bsm[(kk + c4 + 4) * BPAD + col]);
                mma8(acc[0][ni], a[0], b);
                mma8(acc[1][ni], a[1], b);
            }
        }
        __syncthreads();
    }
    // epilogue: bias + scatter. Q fp32; K/V into fp16 packed frag layouts.
    #pragma unroll
    for (int mi = 0; mi < 2; mi++) {
        #pragma unroll
        for (int hh = 0; hh < 2; hh++) {
            int r = wm * 32 + mi * 16 + g + hh * 8;
            int mglob = m0 + r;
            int batch = mglob >> 10, l = mglob & 1023;
            int t = l >> 6;
            #pragma unroll
            for (int ni = 0; ni < 8; ni++) {
                int n = n0 + wn * 64 + ni * 8 + c4 * 2;
                float v0 = acc[mi][ni][hh * 2 + 0] + bias[n];
                float v1 = acc[mi][ni][hh * 2 + 1] + bias[n + 1];
                int h = n / 192;
                int rr = n - h * 192;
                int part = rr >> 6, d = rr & 63;   // d even
                size_t bh = (size_t)(batch * Hn + h);
                if (part == 0) {
                    *(float2*)(g_q + (bh * Ln + l) * DH + d) = make_float2(v0, v1);
                } else if (part == 1) {
                    // K pack: n-col = kv = l, k = d (d,d+1 share a half2 slot)
                    int nf = (l >> 3) & 7, gg = l & 7;
                    int ks0 = d >> 4, kd = d & 15;
                    int c4k = (kd & 7) >> 1, br = kd >> 3;
                    size_t idx = (bh * 16 + t) * 4096 +
                                 (size_t)((ks0 * 8 + nf) * 32 + gg * 4 + c4k) * 4 + br * 2;
                    *(__half2*)(g_kpack + idx) = __floats2half2_rn(v0, v1);
                } else {
                    // V pack: n-col = d, k = kv = l
                    int kv6 = l & 63;
                    int ksv = kv6 >> 4, kdv = kv6 & 15;
                    int c4v = (kdv & 7) >> 1, hxv = kdv & 1, brv = kdv >> 3;
                    size_t base = (bh * 16 + t) * 4096;
                    g_vpack[base + (size_t)((ksv * 8 + (d >> 3)) * 32 + (d & 7) * 4 + c4v) * 4 +
                            brv * 2 + hxv] = __float2half_rn(v0);
                    int dd = d + 1;
                    g_vpack[base + (size_t)((ksv * 8 + (dd >> 3)) * 32 + (dd & 7) * 4 + c4v) * 4 +
                            brv * 2 + hxv] = __float2half_rn(v1);
                }
            }
        }
    }
}

// ---------------- kernel 3: fused attention (fp16 mma, 2 blocks/SM) ----------
#define PSP 72
#define SMB_QS 0            // 16384 halfs = 32768 B
#define SMB_BS 32768        //  8192 halfs = 16384 B
#define SMB_VS 49152        //  4096 halfs =  8192 B
#define SMB_PS 57344        //  128*72 floats = 36864 B
#define SMB_L  94208        //  128 floats = 512 B
#define ATT_SMEM 94720

__device__ __forceinline__ void stage_B(char* smc, int bh, int t, int tid) {
    unsigned dst = (unsigned)__cvta_generic_to_shared(smc + SMB_BS);
    const char* sk = (const char*)(g_kpack + ((size_t)bh * 16 + t) * 4096);
    const char* sp = (const char*)(g_kppack + (size_t)t * 4096);
    #pragma unroll
    for (int p = 0; p < 2; p++) {
        int idx = p * 256 + tid;            // 0..511 chunks of 16B each part
        cpa16(dst + idx * 16, sk + idx * 16);
        cpa16(dst + 8192 + idx * 16, sp + idx * 16);
    }
}
__device__ __forceinline__ void stage_V(char* smc, int bh, int t, int tid) {
    unsigned dst = (unsigned)__cvta_generic_to_shared(smc + SMB_VS);
    const char* sv = (const char*)(g_vpack + ((size_t)bh * 16 + t) * 4096);
    #pragma unroll
    for (int p = 0; p < 2; p++) {
        int idx = p * 256 + tid;
        cpa16(dst + idx * 16, sv + idx * 16);
    }
}

__global__ __launch_bounds__(256, 2) void attn_kernel(float* __restrict__ out) {
    extern __shared__ char smc[];
    __half* Qs  = (__half*)(smc + SMB_QS);   // A-pack [rf 8][ks 8][lane][8]
    __half* Bs  = (__half*)(smc + SMB_BS);   // B-pack [ks 8][nf 8][lane][4]
    __half* Vs  = (__half*)(smc + SMB_VS);   // B-pack [ks 4][nf 8][lane][4]
    float* Ps   = (float*)(smc + SMB_PS);    // [128][PSP]
    float* lrow = (float*)(smc + SMB_L);     // [128]
    int qt = blockIdx.x, bh = blockIdx.y;
    int q0 = qt * 128;
    const float* Qg = g_q + ((size_t)bh << 16);
    int tid = threadIdx.x, lane = tid & 31, wid = tid >> 5;
    int wm = wid >> 1, wn = wid & 1;          // 4 x 2 warps, 32x32 tiles
    int g = lane >> 2, c4 = lane & 3;

    stage_B(smc, bh, 0, tid);
    CP_COMMIT();                               // group: B(0)

    // ---- build Q | Q' (scaled 1/8) into fp16 A-pack ----
    {
        int r = tid >> 1;                      // 0..127
        int half_ = tid & 1;                   // 16 j's each
        const float* src = Qg + (size_t)(q0 + r) * 64 + half_ * 16;
        float qa[16], qb[16];
        #pragma unroll
        for (int i = 0; i < 16; i += 4) {
            float4 v = *(const float4*)(src + i);
            qa[i] = v.x; qa[i+1] = v.y; qa[i+2] = v.z; qa[i+3] = v.w;
            float4 u = *(const float4*)(src + 32 + i);
            qb[i] = u.x; qb[i+1] = u.y; qb[i+2] = u.z; qb[i+3] = u.w;
        }
        float pos = (float)(q0 + r);
        int gg = r & 7, hi = (r >> 3) & 1, rf = r >> 4;
        #pragma unroll
        for (int i = 0; i < 16; i++) {
            int j = half_ * 16 + i;
            float w = expf(-(float)(2 * j) * 0.14391157f);
            float s, c;
            sincosf(pos * w, &s, &c);
            float vals[4] = { 0.125f * qa[i], 0.125f * qb[i],
                              0.125f * (qa[i] * s + qb[i] * c),
                              0.125f * (qb[i] * s - qa[i] * c) };
            #pragma unroll
            for (int q = 0; q < 4; q++) {
                int cc = j + q * 32;
                int ks = cc >> 4, kd = cc & 15;
                int c4q = (kd & 7) >> 1, hx = kd & 1, khi = kd >> 3;
                Qs[((rf * 8 + ks) * 32 + gg * 4 + c4q) * 8 + (khi * 2 + hi) * 2 + hx] =
                    __float2half_rn(vals[q]);
            }
        }
        if (tid < 128) lrow[tid] = 0.0f;
    }

    float acco[2][4][4];
    #pragma unroll
    for (int mi = 0; mi < 2; mi++)
        #pragma unroll
        for (int j = 0; j < 4; j++)
            #pragma unroll
            for (int q = 0; q < 4; q++) acco[mi][j][q] = 0.0f;

    for (int kt = 0; kt < 16; kt++) {
        __syncthreads();                       // A: PV(kt-1) done with Vs/Ps
        stage_V(smc, bh, kt, tid);
        CP_COMMIT();                           // outstanding: {B(kt), V(kt)}
        CP_WAIT(1);                            // B(kt) arrived
        __syncthreads();                       // B: Bs (and Qs at kt=0) visible

        // ---- S = [Q|Q'] . [K|K']^T  (fp16 m16n8k16, k=128 in 8 steps) ----
        float accs[2][4][4];
        #pragma unroll
        for (int mi = 0; mi < 2; mi++)
            #pragma unroll
            for (int j = 0; j < 4; j++)
                #pragma unroll
                for (int q = 0; q < 4; q++) accs[mi][j][q] = 0.0f;
        #pragma unroll
        for (int ks = 0; ks < 8; ks++) {
            uint4 av[2];
            #pragma unroll
            for (int mi = 0; mi < 2; mi++)
                av[mi] = *(const uint4*)(Qs + (((wm * 2 + mi) * 8 + ks) * 32 + lane) * 8);
            #pragma unroll
            for (int ni = 0; ni < 4; ni++) {
                uint2 bv = *(const uint2*)(Bs + ((ks * 8 + wn * 4 + ni) * 32 + lane) * 4);
                mma16(accs[0][ni], av[0], bv);
                mma16(accs[1][ni], av[1], bv);
            }
        }

        // ---- P = exp(S); Ps stores; row sums ----
        #pragma unroll
        for (int mi = 0; mi < 2; mi++)
            #pragma unroll
            for (int hh = 0; hh < 2; hh++) {
                int r = wm * 32 + mi * 16 + g + hh * 8;
                float part = 0.0f;
                #pragma unroll
                for (int ni = 0; ni < 4; ni++) {
                    float p0 = __expf(accs[mi][ni][hh * 2 + 0]);
                    float p1 = __expf(accs[mi][ni][hh * 2 + 1]);
                    part += p0 + p1;
                    *(float2*)(Ps + r * PSP + wn * 32 + ni * 8 + c4 * 2) =
                        make_float2(p0, p1);
                }
                part += __shfl_xor_sync(0xffffffffu, part, 1);
                part += __shfl_xor_sync(0xffffffffu, part, 2);
                if (c4 == 0) atomicAdd(&lrow[r], part);
            }

        CP_WAIT(0);                            // V(kt) arrived
        __syncthreads();                       // C: Vs+Ps visible; Bs reads done
        if (kt < 15) {
            stage_B(smc, bh, kt + 1, tid);
            CP_COMMIT();                       // hidden under PV
        }

        // ---- O += P @ V  (fp16 m16n8k16, kv=64 in 4 steps) ----
        #pragma unroll
        for (int ks = 0; ks < 4; ks++) {
            int kk = ks * 16;
            uint4 ap[2];
            #pragma unroll
            for (int mi = 0; mi < 2; mi++) {
                int r = wm * 32 + mi * 16 + g;
                float2 f0 = *(const float2*)(Ps + r * PSP + kk + 2 * c4);
                float2 f1 = *(const float2*)(Ps + (r + 8) * PSP + kk + 2 * c4);
                float2 f2 = *(const float2*)(Ps + r * PSP + kk + 2 * c4 + 8);
                float2 f3 = *(const float2*)(Ps + (r + 8) * PSP + kk + 2 * c4 + 8);
                ap[mi] = make_uint4(h2u(f0), h2u(f1), h2u(f2), h2u(f3));
            }
            #pragma unroll
            for (int ni = 0; ni < 4; ni++) {
                uint2 bv = *(const uint2*)(Vs + ((ks * 8 + wn * 4 + ni) * 32 + lane) * 4);
                mma16(acco[0][ni], ap[0], bv);
                mma16(acco[1][ni], ap[1], bv);
            }
        }
    }

    // ---- epilogue: O / l, fused transpose to [B, L, D] ----
    int batch = bh >> 3, h = bh & 7;
    #pragma unroll
    for (int mi = 0; mi < 2; mi++)
        #pragma unroll
        for (int hh = 0; hh < 2; hh++) {
            int r = wm * 32 + mi * 16 + g + hh * 8;
            float inv = 1.0f / lrow[r];
            int l = q0 + r;
            #pragma unroll
            for (int ni = 0; ni < 4; ni++) {
                int d = wn * 32 + ni * 8 + c4 * 2;
                *(float2*)(out + ((size_t)(batch * Ln + l)) * Dn + h * DH + d) =
                    make_float2(acco[mi][ni][hh * 2] * inv,
                                acco[mi][ni][hh * 2 + 1] * inv);
            }
        }
}

// ---------------- launch ------------------------------------------------------
extern "C" void kernel_launch(void* const* d_in, const int* in_sizes, int n_in,
                              void* d_out, int out_size) {
    (void)in_sizes; (void)n_in; (void)out_size;
    const float* x    = (const float*)d_in[0];
    const float* W    = (const float*)d_in[1];
    const float* bias = (const float*)d_in[2];
    float* out = (float*)d_out;

    cudaFuncSetAttribute(attn_kernel,
                         cudaFuncAttributeMaxDynamicSharedMemorySize, ATT_SMEM);

    kp_kernel<<<Ln, 64>>>();

    dim3 pg(12, 32);
    proj_kernel<<<pg, 256>>>(x, W, bias);

    dim3 ag(8, BHn);
    attn_kernel<<<ag, 256, ATT_SMEM>>>(out);
}